// round 7
// baseline (speedup 1.0000x reference)
#include <cuda_runtime.h>
#include <math.h>

#define BB 16
#define CCH 256
#define TT 576
#define NH 8
#define QSCALE 0.17677669529663687f
#define GN_EPS 1e-5f

__device__ float g_qt[BB * NH * TT * 32];
__device__ float g_kt[BB * NH * TT * 32];
__device__ float g_vt[BB * NH * TT * 32];
__device__ float g_E[BB * NH * TT * 48];
__device__ float g_P[48 * 256];
__device__ float g_R[NH * 47 * 32];
__device__ float g_att[BB * TT * CCH];
__device__ float g_y[BB * CCH * TT];
__device__ float g_mu[BB * 16];
__device__ float g_rstd[BB * 16];

// ---------- k0: P table (48x256) + R table (8x47x32) ----------
__global__ void k0_prep(const float* __restrict__ rh_v, const float* __restrict__ rw_v,
                        const float* __restrict__ rh_k, const float* __restrict__ rw_k) {
    int bx = blockIdx.x, tid = threadIdx.x;
    if (bx < 48) {
        int idx = bx * 256 + tid;
        int m = idx >> 8, rest = idx & 255;
        g_P[idx] = (m > 0) ? (rh_v[(m - 1) * 256 + rest] + rw_v[(m - 1) * 256 + rest]) : 0.f;
    } else {
        int l = bx - 48;                 // 0..46
        int n = tid >> 5, d = tid & 31;
        g_R[(n * 47 + l) * 32 + d] = rh_k[(l * 8 + n) * 32 + d] + rw_k[(l * 8 + n) * 32 + d];
    }
}

// ---------- k1: qkv GEMM 64x64 tile, fused transpose epilogue ----------
__global__ __launch_bounds__(256) void k1_qkv(const float* __restrict__ x,
                                              const float* __restrict__ w,
                                              const float* __restrict__ bias) {
    int b = blockIdx.z, o0 = blockIdx.y * 64, i0 = blockIdx.x * 64;
    __shared__ float As[16][68], Bs[16][68];
    __shared__ float Ts[64][68];
    float acc[4][4] = {};
    int tid = threadIdx.x, tx = tid % 16, ty = tid / 16;
    const float* xb = x + (size_t)b * CCH * TT;
    for (int c0 = 0; c0 < 256; c0 += 16) {
        int row = tid >> 2, cc = (tid & 3) * 4;
        float4 wv = *(const float4*)&w[(o0 + row) * 256 + c0 + cc];
        As[cc + 0][row] = wv.x; As[cc + 1][row] = wv.y;
        As[cc + 2][row] = wv.z; As[cc + 3][row] = wv.w;
        int cr = tid >> 4, i4 = (tid & 15) * 4;
        *(float4*)&Bs[cr][i4] = *(const float4*)&xb[(c0 + cr) * TT + i0 + i4];
        __syncthreads();
#pragma unroll
        for (int kk = 0; kk < 16; kk++) {
            float a[4], bv[4];
            *(float4*)a  = *(const float4*)&As[kk][ty * 4];
            *(float4*)bv = *(const float4*)&Bs[kk][tx * 4];
#pragma unroll
            for (int r = 0; r < 4; r++)
#pragma unroll
                for (int s = 0; s < 4; s++) acc[r][s] += a[r] * bv[s];
        }
        __syncthreads();
    }
#pragma unroll
    for (int r = 0; r < 4; r++) {
        float bv = bias[o0 + ty * 4 + r];
#pragma unroll
        for (int s = 0; s < 4; s++) Ts[tx * 4 + s][ty * 4 + r] = acc[r][s] + bv;
    }
    __syncthreads();
    int sec = o0 >> 8;                      // 0=q, 1=k, 2=v
    int h0 = (o0 & 255) >> 5;
    float* dst = (sec == 0) ? g_qt : (sec == 1) ? g_kt : g_vt;
    int tl_ = tid >> 2, quad = tid & 3;
#pragma unroll
    for (int k4 = 0; k4 < 4; k4++) {
        int ol = quad * 16 + k4 * 4;
        int head = h0 + (ol >> 5);
        int d = ol & 31;
        float4 v = *(const float4*)&Ts[tl_][ol];
        *(float4*)&dst[(((size_t)b * NH + head) * TT + i0 + tl_) * 32 + d] = v;
    }
}

// ---------- kE: E[bn][iu][l] = qt[bn][iu]·R[n][l] ----------
__global__ __launch_bounds__(256) void kE_gemm() {
    __shared__ float Qs[64][36];
    __shared__ float Rs[48][36];
    int bn = blockIdx.y;
    int iu0 = blockIdx.x * 64;
    int n = bn & 7;
    int tid = threadIdx.x;
    const float* qsrc = g_qt + ((size_t)bn * TT + iu0) * 32;
    for (int idx = tid; idx < 64 * 32; idx += 256) Qs[idx >> 5][idx & 31] = qsrc[idx];
    for (int idx = tid; idx < 48 * 32; idx += 256) {
        int r = idx >> 5, d = idx & 31;
        Rs[r][d] = (r < 47) ? g_R[(n * 47 + r) * 32 + d] : 0.f;
    }
    __syncthreads();
    int tl = tid & 15, tiu = tid >> 4;
    float acc[4][3] = {};
#pragma unroll
    for (int d4 = 0; d4 < 8; d4++) {
        float4 q4[4], r4[3];
#pragma unroll
        for (int r = 0; r < 4; r++) q4[r] = *(const float4*)&Qs[tiu * 4 + r][d4 * 4];
#pragma unroll
        for (int j = 0; j < 3; j++) r4[j] = *(const float4*)&Rs[tl * 3 + j][d4 * 4];
#pragma unroll
        for (int r = 0; r < 4; r++)
#pragma unroll
            for (int j = 0; j < 3; j++)
                acc[r][j] += q4[r].x * r4[j].x + q4[r].y * r4[j].y +
                             q4[r].z * r4[j].z + q4[r].w * r4[j].w;
    }
    float* ep = g_E + ((size_t)bn * TT + iu0) * 48;
#pragma unroll
    for (int r = 0; r < 4; r++)
#pragma unroll
        for (int j = 0; j < 3; j++)
            ep[(tiu * 4 + r) * 48 + tl * 3 + j] = acc[r][j];
}

// ---------- k3: fused attention — i-tile 8, 3 CTAs/SM ----------
__global__ __launch_bounds__(256, 3) void k3_attn() {
    extern __shared__ float sm[];
    float* q_s  = sm;            // [8][8][32]    2048
    float* z_s  = sm + 2048;     // [8][32][12]   3072
    float* A_s  = sm + 5120;     // [8][8][25]    1600
    float* bd_s = sm + 6720;     // [8][8][24]    1536
    int b = blockIdx.y, i0 = blockIdx.x * 8;
    int tid = threadIdx.x, warp = tid >> 5, lane = tid & 31;

    {   // coalesced q tile load
        const float* qt = g_qt + (((size_t)b * NH + warp) * TT + i0) * 32;
#pragma unroll
        for (int ii = 0; ii < 8; ii++) q_s[(warp * 8 + ii) * 32 + lane] = qt[ii * 32 + lane];
    }
    for (int idx = tid; idx < 8 * 8 * 24; idx += 256) {
        int n = idx / 192, r = idx % 192, ii = r / 24, c = r % 24;
        int ig = i0 + ii;
        int diff = c - ig;
        int fl = (diff >= 0) ? 0 : -((-diff + 47) / 48);
        int l = diff - 48 * fl;
        int iu = 12 + ig + fl;
        bd_s[idx] = l ? g_E[(((size_t)b * NH + n) * TT + iu) * 48 + (l - 1)] : 0.f;
    }
    for (int idx = tid; idx < 8 * 8 * 25; idx += 256) A_s[idx] = 0.f;

    float acc[8];
#pragma unroll
    for (int ii = 0; ii < 8; ii++) acc[ii] = 0.f;
    __syncthreads();

    for (int jt = 0; jt < TT; jt += 32) {
        {   // logits: warp = head n, lane = j
            int n = warp, j = jt + lane, c = j % 24;
            const float4* kp = (const float4*)(g_kt + (((size_t)b * NH + n) * TT + j) * 32);
            float4 kr[8];
#pragma unroll
            for (int q4 = 0; q4 < 8; q4++) kr[q4] = kp[q4];
#pragma unroll
            for (int ii = 0; ii < 8; ii++) {
                const float4* qv = (const float4*)&q_s[(n * 8 + ii) * 32];
                float s = 0.f;
#pragma unroll
                for (int q4 = 0; q4 < 8; q4++) {
                    float4 qq = qv[q4];
                    s += qq.x * kr[q4].x + qq.y * kr[q4].y + qq.z * kr[q4].z + qq.w * kr[q4].w;
                }
                z_s[(n * 32 + lane) * 12 + ii] = s + bd_s[(n * 8 + ii) * 24 + c];
            }
        }
        __syncthreads();
        {   // softmax over heads at each (i,j): thread = (j, i)
            int j = tid & 31, i = tid >> 5;
            float zz[8];
#pragma unroll
            for (int n = 0; n < 8; n++) zz[n] = z_s[(n * 32 + j) * 12 + i] * QSCALE;
            float mx = zz[0];
#pragma unroll
            for (int n = 1; n < 8; n++) mx = fmaxf(mx, zz[n]);
            float e[8], s = 0.f;
#pragma unroll
            for (int n = 0; n < 8; n++) { e[n] = __expf(zz[n] - mx); s += e[n]; }
            float inv = 1.f / s;
#pragma unroll
            for (int n = 0; n < 8; n++) z_s[(n * 32 + j) * 12 + i] = e[n] * inv;
        }
        __syncthreads();
        {   // A-sums: owner RMW per head-warp (j and j+24 share c)
            int n = warp, c = (jt + lane) % 24;
            if (lane < 24) {
#pragma unroll
                for (int ii = 0; ii < 8; ii++)
                    A_s[(n * 8 + ii) * 25 + c] += z_s[(n * 32 + lane) * 12 + ii];
            }
            __syncwarp();
            if (lane >= 24) {
#pragma unroll
                for (int ii = 0; ii < 8; ii++)
                    A_s[(n * 8 + ii) * 25 + c] += z_s[(n * 32 + lane) * 12 + ii];
            }
        }
        {   // attn @ v: warp = head n, lane = d
            int n = warp, d = lane;
            const float* vp = g_vt + (((size_t)b * NH + n) * TT + jt) * 32 + d;
#pragma unroll 4
            for (int jj = 0; jj < 32; jj++) {
                float v = vp[jj * 32];
                const float4* ap = (const float4*)&z_s[(n * 32 + jj) * 12];
#pragma unroll
                for (int q4 = 0; q4 < 2; q4++) {
                    float4 a = ap[q4];
                    acc[q4 * 4 + 0] += a.x * v; acc[q4 * 4 + 1] += a.y * v;
                    acc[q4 * 4 + 2] += a.z * v; acc[q4 * 4 + 3] += a.w * v;
                }
            }
        }
        __syncthreads();
    }
    {   // epilogue: positional-value term
        int n = warp, d = lane;
#pragma unroll
        for (int ii = 0; ii < 8; ii++) {
            int ig = i0 + ii;
            float o2 = 0.f;
#pragma unroll
            for (int c = 0; c < 24; c++) {
                int m = (c - ig) % 48; if (m < 0) m += 48;
                o2 += A_s[(n * 8 + ii) * 25 + c] * g_P[m * 256 + n * 32 + d];
            }
            g_att[((size_t)b * TT + ig) * CCH + n * 32 + d] = acc[ii] + o2;
        }
    }
}

// ---------- k4: fc GEMM + residual ----------
__global__ __launch_bounds__(256) void k4_fc(const float* __restrict__ x,
                                             const float* __restrict__ w,
                                             const float* __restrict__ bias) {
    int b = blockIdx.z, o0 = blockIdx.y * 64, i0 = blockIdx.x * 64;
    __shared__ float As[16][68], Bs[16][68];
    float acc[4][4] = {};
    int tid = threadIdx.x, tx = tid % 16, ty = tid / 16;
    const float* att = g_att + (size_t)b * TT * CCH;
    for (int c0 = 0; c0 < 256; c0 += 16) {
        int row = tid >> 2, cc = (tid & 3) * 4;
        float4 wv = *(const float4*)&w[(o0 + row) * 256 + c0 + cc];
        As[cc + 0][row] = wv.x; As[cc + 1][row] = wv.y;
        As[cc + 2][row] = wv.z; As[cc + 3][row] = wv.w;
        float4 av = *(const float4*)&att[(i0 + row) * 256 + c0 + cc];
        Bs[cc + 0][row] = av.x; Bs[cc + 1][row] = av.y;
        Bs[cc + 2][row] = av.z; Bs[cc + 3][row] = av.w;
        __syncthreads();
#pragma unroll
        for (int kk = 0; kk < 16; kk++) {
            float a[4], bv[4];
            *(float4*)a  = *(const float4*)&As[kk][ty * 4];
            *(float4*)bv = *(const float4*)&Bs[kk][tx * 4];
#pragma unroll
            for (int r = 0; r < 4; r++)
#pragma unroll
                for (int s = 0; s < 4; s++) acc[r][s] += a[r] * bv[s];
        }
        __syncthreads();
    }
#pragma unroll
    for (int r = 0; r < 4; r++) {
        int o = o0 + ty * 4 + r;
        float bv = bias[o];
        float4 xv = *(const float4*)&x[((size_t)b * CCH + o) * TT + i0 + tx * 4];
        *(float4*)&g_y[((size_t)b * CCH + o) * TT + i0 + tx * 4] =
            make_float4(acc[r][0] + bv + xv.x, acc[r][1] + bv + xv.y,
                        acc[r][2] + bv + xv.z, acc[r][3] + bv + xv.w);
    }
}

__global__ void k5_gnstats() {
    int bid = blockIdx.x, b = bid >> 4, g = bid & 15;
    const float* yp = g_y + ((size_t)(b * CCH + g * 16)) * TT;
    int tid = threadIdx.x;
    float s = 0.f, sq = 0.f;
    for (int idx = tid; idx < 16 * TT; idx += 256) { float v = yp[idx]; s += v; sq += v * v; }
#pragma unroll
    for (int off = 16; off > 0; off >>= 1) {
        s  += __shfl_down_sync(0xffffffffu, s, off);
        sq += __shfl_down_sync(0xffffffffu, sq, off);
    }
    __shared__ float rs[8], rq[8];
    if ((tid & 31) == 0) { rs[tid >> 5] = s; rq[tid >> 5] = sq; }
    __syncthreads();
    if (tid == 0) {
        float S = 0.f, Q = 0.f;
#pragma unroll
        for (int w = 0; w < 8; w++) { S += rs[w]; Q += rq[w]; }
        float mu = S / 9216.f;
        float var = Q / 9216.f - mu * mu;
        g_mu[bid] = mu;
        g_rstd[bid] = rsqrtf(var + GN_EPS);
    }
}

__global__ void k6_gnapply(float* __restrict__ out, const float* __restrict__ gw,
                           const float* __restrict__ gb) {
    int idx = blockIdx.x * 256 + threadIdx.x;
    int o = (idx / TT) & 255;
    int b = idx / (TT * CCH);
    float mu = g_mu[b * 16 + (o >> 4)], rstd = g_rstd[b * 16 + (o >> 4)];
    out[idx] = (g_y[idx] - mu) * rstd * gw[o] + gb[o];
}

extern "C" void kernel_launch(void* const* d_in, const int* in_sizes, int n_in,
                              void* d_out, int out_size) {
    const float* x     = (const float*)d_in[0];
    const float* qkv_w = (const float*)d_in[1];
    const float* qkv_b = (const float*)d_in[2];
    const float* rh_k  = (const float*)d_in[3];
    const float* rw_k  = (const float*)d_in[4];
    const float* rh_v  = (const float*)d_in[5];
    const float* rw_v  = (const float*)d_in[6];
    const float* fc_w  = (const float*)d_in[7];
    const float* fc_b  = (const float*)d_in[8];
    const float* gn_w  = (const float*)d_in[9];
    const float* gn_b  = (const float*)d_in[10];
    float* out = (float*)d_out;

    cudaFuncSetAttribute(k3_attn, cudaFuncAttributeMaxDynamicSharedMemorySize, 33024);

    k0_prep<<<95, 256>>>(rh_v, rw_v, rh_k, rw_k);
    k1_qkv<<<dim3(9, 12, BB), 256>>>(x, qkv_w, qkv_b);
    kE_gemm<<<dim3(9, 128), 256>>>();
    k3_attn<<<dim3(72, BB), 256, 33024>>>();
    k4_fc<<<dim3(9, 4, BB), 256>>>(x, fc_w, fc_b);
    k5_gnstats<<<256, 256>>>();
    k6_gnapply<<<9216, 256>>>(out, gn_w, gn_b);
}

// round 8
// speedup vs baseline: 1.3028x; 1.3028x over previous
#include <cuda_runtime.h>
#include <cuda_bf16.h>
#include <math.h>

#define BB 16
#define CCH 256
#define TT 576
#define NH 8
#define QSCALE 0.17677669529663687f
#define GN_EPS 1e-5f

__device__ float g_qt[BB * NH * TT * 32];
__device__ unsigned g_kh[BB * NH * TT * 16];   // bf16x2 d-pairs, [bn][t][dp]
__device__ unsigned g_kl[BB * NH * TT * 16];
__device__ unsigned g_vh[BB * NH * 32 * 288];  // bf16x2 j-pairs, [bn][d][jp]
__device__ unsigned g_vl[BB * NH * 32 * 288];
__device__ float g_E[BB * NH * TT * 48];
__device__ float g_P[48 * 256];
__device__ float g_R[NH * 47 * 32];
__device__ float g_att[BB * TT * CCH];
__device__ float g_y[BB * CCH * TT];
__device__ float g_mu[BB * 16];
__device__ float g_rstd[BB * 16];

__device__ __forceinline__ unsigned pack_bf16(float x, float y) {
    __nv_bfloat162 t = __floats2bfloat162_rn(x, y);
    return *reinterpret_cast<unsigned*>(&t);
}
__device__ __forceinline__ void split_pair(float x, float y, unsigned& hi, unsigned& lo) {
    float xh = __bfloat162float(__float2bfloat16_rn(x));
    float yh = __bfloat162float(__float2bfloat16_rn(y));
    hi = pack_bf16(xh, yh);
    lo = pack_bf16(x - xh, y - yh);
}
__device__ __forceinline__ void mma_bf16(float* d, const unsigned* a, const unsigned* b) {
    asm volatile("mma.sync.aligned.m16n8k16.row.col.f32.bf16.bf16.f32 "
                 "{%0,%1,%2,%3},{%4,%5,%6,%7},{%8,%9},{%0,%1,%2,%3};"
                 : "+f"(d[0]), "+f"(d[1]), "+f"(d[2]), "+f"(d[3])
                 : "r"(a[0]), "r"(a[1]), "r"(a[2]), "r"(a[3]), "r"(b[0]), "r"(b[1]));
}

// ---------- k0 ----------
__global__ void k0_prep(const float* __restrict__ rh_v, const float* __restrict__ rw_v,
                        const float* __restrict__ rh_k, const float* __restrict__ rw_k) {
    int bx = blockIdx.x, tid = threadIdx.x;
    if (bx < 48) {
        int idx = bx * 256 + tid;
        int m = idx >> 8, rest = idx & 255;
        g_P[idx] = (m > 0) ? (rh_v[(m - 1) * 256 + rest] + rw_v[(m - 1) * 256 + rest]) : 0.f;
    } else {
        int l = bx - 48;
        int n = tid >> 5, d = tid & 31;
        g_R[(n * 47 + l) * 32 + d] = rh_k[(l * 8 + n) * 32 + d] + rw_k[(l * 8 + n) * 32 + d];
    }
}

// ---------- k1: qkv GEMM, epilogue emits q f32 / k,v bf16-split layouts ----------
__global__ __launch_bounds__(256) void k1_qkv(const float* __restrict__ x,
                                              const float* __restrict__ w,
                                              const float* __restrict__ bias) {
    int b = blockIdx.z, o0 = blockIdx.y * 64, i0 = blockIdx.x * 64;
    __shared__ float As[16][68], Bs[16][68];
    __shared__ float Ts[64][68];
    float acc[4][4] = {};
    int tid = threadIdx.x, tx = tid % 16, ty = tid / 16;
    const float* xb = x + (size_t)b * CCH * TT;
    for (int c0 = 0; c0 < 256; c0 += 16) {
        int row = tid >> 2, cc = (tid & 3) * 4;
        float4 wv = *(const float4*)&w[(o0 + row) * 256 + c0 + cc];
        As[cc + 0][row] = wv.x; As[cc + 1][row] = wv.y;
        As[cc + 2][row] = wv.z; As[cc + 3][row] = wv.w;
        int cr = tid >> 4, i4 = (tid & 15) * 4;
        *(float4*)&Bs[cr][i4] = *(const float4*)&xb[(c0 + cr) * TT + i0 + i4];
        __syncthreads();
#pragma unroll
        for (int kk = 0; kk < 16; kk++) {
            float a[4], bv[4];
            *(float4*)a  = *(const float4*)&As[kk][ty * 4];
            *(float4*)bv = *(const float4*)&Bs[kk][tx * 4];
#pragma unroll
            for (int r = 0; r < 4; r++)
#pragma unroll
                for (int s = 0; s < 4; s++) acc[r][s] += a[r] * bv[s];
        }
        __syncthreads();
    }
#pragma unroll
    for (int r = 0; r < 4; r++) {
        float bv = bias[o0 + ty * 4 + r];
#pragma unroll
        for (int s = 0; s < 4; s++) Ts[tx * 4 + s][ty * 4 + r] = acc[r][s] + bv;
    }
    __syncthreads();
    int sec = o0 >> 8;                  // 0=q, 1=k, 2=v
    int h0 = (o0 & 255) >> 5;
    if (sec == 0) {
        int tl_ = tid >> 2, quad = tid & 3;
#pragma unroll
        for (int k4 = 0; k4 < 4; k4++) {
            int ol = quad * 16 + k4 * 4;
            int head = h0 + (ol >> 5);
            int d = ol & 31;
            float4 v = *(const float4*)&Ts[tl_][ol];
            *(float4*)&g_qt[(((size_t)b * NH + head) * TT + i0 + tl_) * 32 + d] = v;
        }
    } else if (sec == 1) {
#pragma unroll
        for (int wI = 0; wI < 8; wI++) {
            int idx = tid + 256 * wI;
            int hh = idx >> 10, tl = (idx >> 4) & 63, dp = idx & 15;
            float xv = Ts[tl][hh * 32 + 2 * dp], yv = Ts[tl][hh * 32 + 2 * dp + 1];
            unsigned hi, lo; split_pair(xv, yv, hi, lo);
            size_t a = (((size_t)b * NH + h0 + hh) * TT + i0 + tl) * 16 + dp;
            g_kh[a] = hi; g_kl[a] = lo;
        }
    } else {
#pragma unroll
        for (int wI = 0; wI < 8; wI++) {
            int idx = tid + 256 * wI;
            int hh = idx >> 10, dd = (idx >> 5) & 31, jp = idx & 31;
            float xv = Ts[2 * jp][hh * 32 + dd], yv = Ts[2 * jp + 1][hh * 32 + dd];
            unsigned hi, lo; split_pair(xv, yv, hi, lo);
            size_t a = (((size_t)b * NH + h0 + hh) * 32 + dd) * 288 + (i0 >> 1) + jp;
            g_vh[a] = hi; g_vl[a] = lo;
        }
    }
}

// ---------- kE ----------
__global__ __launch_bounds__(256) void kE_gemm() {
    __shared__ float Qs[64][36];
    __shared__ float Rs[48][36];
    int bn = blockIdx.y;
    int iu0 = blockIdx.x * 64;
    int n = bn & 7;
    int tid = threadIdx.x;
    const float* qsrc = g_qt + ((size_t)bn * TT + iu0) * 32;
    for (int idx = tid; idx < 64 * 32; idx += 256) Qs[idx >> 5][idx & 31] = qsrc[idx];
    for (int idx = tid; idx < 48 * 32; idx += 256) {
        int r = idx >> 5, d = idx & 31;
        Rs[r][d] = (r < 47) ? g_R[(n * 47 + r) * 32 + d] : 0.f;
    }
    __syncthreads();
    int tl = tid & 15, tiu = tid >> 4;
    float acc[4][3] = {};
#pragma unroll
    for (int d4 = 0; d4 < 8; d4++) {
        float4 q4[4], r4[3];
#pragma unroll
        for (int r = 0; r < 4; r++) q4[r] = *(const float4*)&Qs[tiu * 4 + r][d4 * 4];
#pragma unroll
        for (int j = 0; j < 3; j++) r4[j] = *(const float4*)&Rs[tl * 3 + j][d4 * 4];
#pragma unroll
        for (int r = 0; r < 4; r++)
#pragma unroll
            for (int j = 0; j < 3; j++)
                acc[r][j] += q4[r].x * r4[j].x + q4[r].y * r4[j].y +
                             q4[r].z * r4[j].z + q4[r].w * r4[j].w;
    }
    float* ep = g_E + ((size_t)bn * TT + iu0) * 48;
#pragma unroll
    for (int r = 0; r < 4; r++)
#pragma unroll
        for (int j = 0; j < 3; j++)
            ep[(tiu * 4 + r) * 48 + tl * 3 + j] = acc[r][j];
}

// ---------- k3: fused attention via bf16-split mma ----------
__global__ __launch_bounds__(256) void k3_attn() {
    extern __shared__ float sm[];
    float* z_s  = sm;            // [8][32][20] 5120 floats
    float* A_s  = sm + 5120;     // [8][16][25] 3200
    float* bd_s = sm + 8320;     // [8][16][24] 3072
    int b = blockIdx.y, i0 = blockIdx.x * 16;
    int tid = threadIdx.x, warp = tid >> 5, lane = tid & 31;
    int n = warp, bn = b * NH + n;
    int qr = lane >> 2, qc = lane & 3;

    for (int idx = tid; idx < 8 * 16 * 24; idx += 256) {
        int nn = idx / 384, r = idx % 384, ii = r / 24, c = r % 24;
        int ig = i0 + ii;
        int diff = c - ig;
        int fl = (diff >= 0) ? 0 : -((-diff + 47) / 48);
        int l = diff - 48 * fl;
        int iu = 12 + ig + fl;
        bd_s[idx] = l ? g_E[(((size_t)b * NH + nn) * TT + iu) * 48 + (l - 1)] : 0.f;
    }
    for (int idx = tid; idx < 8 * 16 * 25; idx += 256) A_s[idx] = 0.f;

    // q A-fragments (hi/lo), loaded once
    unsigned qh[2][4], ql[2][4];
#pragma unroll
    for (int kk = 0; kk < 2; kk++)
#pragma unroll
        for (int r = 0; r < 4; r++) {
            int row = i0 + qr + (r & 1) * 8;
            int col = 16 * kk + 2 * qc + (r >> 1) * 8;
            float2 v = *(const float2*)&g_qt[((size_t)bn * TT + row) * 32 + col];
            split_pair(v.x, v.y, qh[kk][r], ql[kk][r]);
        }

    float oacc[4][4];
#pragma unroll
    for (int df = 0; df < 4; df++)
#pragma unroll
        for (int r = 0; r < 4; r++) oacc[df][r] = 0.f;
    __syncthreads();

    for (int jt = 0; jt < TT; jt += 32) {
        int jtc = jt % 24;
        // ---- logits via mma ----
#pragma unroll
        for (int jf = 0; jf < 4; jf++) {
            float z[4] = {0.f, 0.f, 0.f, 0.f};
#pragma unroll
            for (int kk = 0; kk < 2; kk++) {
                size_t base = ((size_t)bn * TT + jt + 8 * jf + qr) * 16 + qc + 8 * kk;
                unsigned bh[2] = {g_kh[base], g_kh[base + 4]};
                unsigned bl[2] = {g_kl[base], g_kl[base + 4]};
                mma_bf16(z, qh[kk], bh);
                mma_bf16(z, qh[kk], bl);
                mma_bf16(z, ql[kk], bh);
            }
            int jl0 = 8 * jf + 2 * qc;
            int c0 = jtc + jl0;     if (c0 >= 24) c0 -= 24; if (c0 >= 24) c0 -= 24;
            int c1 = jtc + jl0 + 1; if (c1 >= 24) c1 -= 24; if (c1 >= 24) c1 -= 24;
            z[0] += bd_s[(n * 16 + qr) * 24 + c0];
            z[1] += bd_s[(n * 16 + qr) * 24 + c1];
            z[2] += bd_s[(n * 16 + qr + 8) * 24 + c0];
            z[3] += bd_s[(n * 16 + qr + 8) * 24 + c1];
            z_s[(n * 32 + jl0) * 20 + qr]         = z[0];
            z_s[(n * 32 + jl0 + 1) * 20 + qr]     = z[1];
            z_s[(n * 32 + jl0) * 20 + qr + 8]     = z[2];
            z_s[(n * 32 + jl0 + 1) * 20 + qr + 8] = z[3];
        }
        __syncthreads();
        // ---- softmax over heads at each (i,j) ----
        {
            int j = tid & 31, ibase = tid >> 5;
#pragma unroll
            for (int p = 0; p < 2; p++) {
                int i = ibase + 8 * p;
                float zz[8];
#pragma unroll
                for (int m = 0; m < 8; m++) zz[m] = z_s[(m * 32 + j) * 20 + i] * QSCALE;
                float mx = zz[0];
#pragma unroll
                for (int m = 1; m < 8; m++) mx = fmaxf(mx, zz[m]);
                float e[8], s = 0.f;
#pragma unroll
                for (int m = 0; m < 8; m++) { e[m] = __expf(zz[m] - mx); s += e[m]; }
                float inv = 1.f / s;
#pragma unroll
                for (int m = 0; m < 8; m++) z_s[(m * 32 + j) * 20 + i] = e[m] * inv;
            }
        }
        __syncthreads();
        // ---- A-sums: owner RMW per head-warp ----
        {
            int c = (jt + lane) % 24;
            if (lane < 24) {
#pragma unroll
                for (int ii = 0; ii < 16; ii++)
                    A_s[(n * 16 + ii) * 25 + c] += z_s[(n * 32 + lane) * 20 + ii];
            }
            __syncwarp();
            if (lane >= 24) {
#pragma unroll
                for (int ii = 0; ii < 16; ii++)
                    A_s[(n * 16 + ii) * 25 + c] += z_s[(n * 32 + lane) * 20 + ii];
            }
        }
        // ---- attn @ v via mma ----
        unsigned ah[2][4], al[2][4];
#pragma unroll
        for (int kk = 0; kk < 2; kk++)
#pragma unroll
            for (int r = 0; r < 4; r++) {
                int jb = 16 * kk + 2 * qc + (r >> 1) * 8;
                int ir = qr + (r & 1) * 8;
                float xv = z_s[(n * 32 + jb) * 20 + ir];
                float yv = z_s[(n * 32 + jb + 1) * 20 + ir];
                split_pair(xv, yv, ah[kk][r], al[kk][r]);
            }
#pragma unroll
        for (int df = 0; df < 4; df++) {
#pragma unroll
            for (int kk = 0; kk < 2; kk++) {
                size_t base = ((size_t)bn * 32 + qr + 8 * df) * 288 + (jt >> 1) + qc + 8 * kk;
                unsigned bh[2] = {g_vh[base], g_vh[base + 4]};
                unsigned bl[2] = {g_vl[base], g_vl[base + 4]};
                mma_bf16(oacc[df], ah[kk], bh);
                mma_bf16(oacc[df], ah[kk], bl);
                mma_bf16(oacc[df], al[kk], bh);
            }
        }
        __syncthreads();
    }
    // ---- epilogue: positional-value term + store ----
#pragma unroll
    for (int df = 0; df < 4; df++)
#pragma unroll
        for (int r = 0; r < 4; r++) {
            int ii = qr + (r >> 1) * 8;
            int d  = 8 * df + 2 * qc + (r & 1);
            int ig = i0 + ii;
            float o2 = 0.f;
#pragma unroll
            for (int c = 0; c < 24; c++) {
                int m = (c - ig) % 48; if (m < 0) m += 48;
                o2 += A_s[(n * 16 + ii) * 25 + c] * g_P[m * 256 + n * 32 + d];
            }
            g_att[((size_t)b * TT + ig) * CCH + n * 32 + d] = oacc[df][r] + o2;
        }
}

// ---------- k4 ----------
__global__ __launch_bounds__(256) void k4_fc(const float* __restrict__ x,
                                             const float* __restrict__ w,
                                             const float* __restrict__ bias) {
    int b = blockIdx.z, o0 = blockIdx.y * 64, i0 = blockIdx.x * 64;
    __shared__ float As[16][68], Bs[16][68];
    float acc[4][4] = {};
    int tid = threadIdx.x, tx = tid % 16, ty = tid / 16;
    const float* att = g_att + (size_t)b * TT * CCH;
    for (int c0 = 0; c0 < 256; c0 += 16) {
        int row = tid >> 2, cc = (tid & 3) * 4;
        float4 wv = *(const float4*)&w[(o0 + row) * 256 + c0 + cc];
        As[cc + 0][row] = wv.x; As[cc + 1][row] = wv.y;
        As[cc + 2][row] = wv.z; As[cc + 3][row] = wv.w;
        float4 av = *(const float4*)&att[(i0 + row) * 256 + c0 + cc];
        Bs[cc + 0][row] = av.x; Bs[cc + 1][row] = av.y;
        Bs[cc + 2][row] = av.z; Bs[cc + 3][row] = av.w;
        __syncthreads();
#pragma unroll
        for (int kk = 0; kk < 16; kk++) {
            float a[4], bv[4];
            *(float4*)a  = *(const float4*)&As[kk][ty * 4];
            *(float4*)bv = *(const float4*)&Bs[kk][tx * 4];
#pragma unroll
            for (int r = 0; r < 4; r++)
#pragma unroll
                for (int s = 0; s < 4; s++) acc[r][s] += a[r] * bv[s];
        }
        __syncthreads();
    }
#pragma unroll
    for (int r = 0; r < 4; r++) {
        int o = o0 + ty * 4 + r;
        float bv = bias[o];
        float4 xv = *(const float4*)&x[((size_t)b * CCH + o) * TT + i0 + tx * 4];
        *(float4*)&g_y[((size_t)b * CCH + o) * TT + i0 + tx * 4] =
            make_float4(acc[r][0] + bv + xv.x, acc[r][1] + bv + xv.y,
                        acc[r][2] + bv + xv.z, acc[r][3] + bv + xv.w);
    }
}

__global__ void k5_gnstats() {
    int bid = blockIdx.x, b = bid >> 4, g = bid & 15;
    const float* yp = g_y + ((size_t)(b * CCH + g * 16)) * TT;
    int tid = threadIdx.x;
    float s = 0.f, sq = 0.f;
    for (int idx = tid; idx < 16 * TT; idx += 256) { float v = yp[idx]; s += v; sq += v * v; }
#pragma unroll
    for (int off = 16; off > 0; off >>= 1) {
        s  += __shfl_down_sync(0xffffffffu, s, off);
        sq += __shfl_down_sync(0xffffffffu, sq, off);
    }
    __shared__ float rs[8], rq[8];
    if ((tid & 31) == 0) { rs[tid >> 5] = s; rq[tid >> 5] = sq; }
    __syncthreads();
    if (tid == 0) {
        float S = 0.f, Q = 0.f;
#pragma unroll
        for (int w = 0; w < 8; w++) { S += rs[w]; Q += rq[w]; }
        float mu = S / 9216.f;
        float var = Q / 9216.f - mu * mu;
        g_mu[bid] = mu;
        g_rstd[bid] = rsqrtf(var + GN_EPS);
    }
}

__global__ void k6_gnapply(float* __restrict__ out, const float* __restrict__ gw,
                           const float* __restrict__ gb) {
    int idx = blockIdx.x * 256 + threadIdx.x;
    int o = (idx / TT) & 255;
    int b = idx / (TT * CCH);
    float mu = g_mu[b * 16 + (o >> 4)], rstd = g_rstd[b * 16 + (o >> 4)];
    out[idx] = (g_y[idx] - mu) * rstd * gw[o] + gb[o];
}

extern "C" void kernel_launch(void* const* d_in, const int* in_sizes, int n_in,
                              void* d_out, int out_size) {
    const float* x     = (const float*)d_in[0];
    const float* qkv_w = (const float*)d_in[1];
    const float* qkv_b = (const float*)d_in[2];
    const float* rh_k  = (const float*)d_in[3];
    const float* rw_k  = (const float*)d_in[4];
    const float* rh_v  = (const float*)d_in[5];
    const float* rw_v  = (const float*)d_in[6];
    const float* fc_w  = (const float*)d_in[7];
    const float* fc_b  = (const float*)d_in[8];
    const float* gn_w  = (const float*)d_in[9];
    const float* gn_b  = (const float*)d_in[10];
    float* out = (float*)d_out;

    cudaFuncSetAttribute(k3_attn, cudaFuncAttributeMaxDynamicSharedMemorySize, 45568);

    k0_prep<<<95, 256>>>(rh_v, rw_v, rh_k, rw_k);
    k1_qkv<<<dim3(9, 12, BB), 256>>>(x, qkv_w, qkv_b);
    kE_gemm<<<dim3(9, 128), 256>>>();
    k3_attn<<<dim3(36, BB), 256, 45568>>>();
    k4_fc<<<dim3(9, 4, BB), 256>>>(x, fc_w, fc_b);
    k5_gnstats<<<256, 256>>>();
    k6_gnapply<<<9216, 256>>>(out, gn_w, gn_b);
}

// round 9
// speedup vs baseline: 1.3932x; 1.0694x over previous
#include <cuda_runtime.h>
#include <cuda_bf16.h>
#include <math.h>

#define BB 16
#define CCH 256
#define TT 576
#define NH 8
#define QSCALE 0.17677669529663687f
#define GN_EPS 1e-5f
#define ZS 17

__device__ float g_qt[BB * NH * TT * 32];
__device__ unsigned g_kh[BB * NH * TT * 16];   // bf16x2 d-pairs, [bn][t][dp]
__device__ unsigned g_kl[BB * NH * TT * 16];
__device__ unsigned g_vh[BB * NH * 32 * 288];  // bf16x2 j-pairs, [bn][d][jp]
__device__ unsigned g_vl[BB * NH * 32 * 288];
__device__ float g_E[BB * NH * TT * 48];
__device__ float g_P[48 * 256];
__device__ float g_R[NH * 47 * 32];
__device__ float g_att[BB * TT * CCH];
__device__ float g_y[BB * CCH * TT];
__device__ float g_mu[BB * 16];
__device__ float g_rstd[BB * 16];

__device__ __forceinline__ unsigned pack_bf16(float x, float y) {
    __nv_bfloat162 t = __floats2bfloat162_rn(x, y);
    return *reinterpret_cast<unsigned*>(&t);
}
__device__ __forceinline__ void split_pair(float x, float y, unsigned& hi, unsigned& lo) {
    float xh = __bfloat162float(__float2bfloat16_rn(x));
    float yh = __bfloat162float(__float2bfloat16_rn(y));
    hi = pack_bf16(xh, yh);
    lo = pack_bf16(x - xh, y - yh);
}
__device__ __forceinline__ void mma_bf16(float* d, const unsigned* a, const unsigned* b) {
    asm volatile("mma.sync.aligned.m16n8k16.row.col.f32.bf16.bf16.f32 "
                 "{%0,%1,%2,%3},{%4,%5,%6,%7},{%8,%9},{%0,%1,%2,%3};"
                 : "+f"(d[0]), "+f"(d[1]), "+f"(d[2]), "+f"(d[3])
                 : "r"(a[0]), "r"(a[1]), "r"(a[2]), "r"(a[3]), "r"(b[0]), "r"(b[1]));
}

// ---------- k0 ----------
__global__ void k0_prep(const float* __restrict__ rh_v, const float* __restrict__ rw_v,
                        const float* __restrict__ rh_k, const float* __restrict__ rw_k) {
    int bx = blockIdx.x, tid = threadIdx.x;
    if (bx < 48) {
        int idx = bx * 256 + tid;
        int m = idx >> 8, rest = idx & 255;
        g_P[idx] = (m > 0) ? (rh_v[(m - 1) * 256 + rest] + rw_v[(m - 1) * 256 + rest]) : 0.f;
    } else {
        int l = bx - 48;
        int n = tid >> 5, d = tid & 31;
        g_R[(n * 47 + l) * 32 + d] = rh_k[(l * 8 + n) * 32 + d] + rw_k[(l * 8 + n) * 32 + d];
    }
}

// ---------- k1: qkv GEMM, epilogue emits q f32 / k,v bf16-split layouts ----------
__global__ __launch_bounds__(256) void k1_qkv(const float* __restrict__ x,
                                              const float* __restrict__ w,
                                              const float* __restrict__ bias) {
    int b = blockIdx.z, o0 = blockIdx.y * 64, i0 = blockIdx.x * 64;
    __shared__ float As[16][68], Bs[16][68];
    __shared__ float Ts[64][68];
    float acc[4][4] = {};
    int tid = threadIdx.x, tx = tid % 16, ty = tid / 16;
    const float* xb = x + (size_t)b * CCH * TT;
    for (int c0 = 0; c0 < 256; c0 += 16) {
        int row = tid >> 2, cc = (tid & 3) * 4;
        float4 wv = *(const float4*)&w[(o0 + row) * 256 + c0 + cc];
        As[cc + 0][row] = wv.x; As[cc + 1][row] = wv.y;
        As[cc + 2][row] = wv.z; As[cc + 3][row] = wv.w;
        int cr = tid >> 4, i4 = (tid & 15) * 4;
        *(float4*)&Bs[cr][i4] = *(const float4*)&xb[(c0 + cr) * TT + i0 + i4];
        __syncthreads();
#pragma unroll
        for (int kk = 0; kk < 16; kk++) {
            float a[4], bv[4];
            *(float4*)a  = *(const float4*)&As[kk][ty * 4];
            *(float4*)bv = *(const float4*)&Bs[kk][tx * 4];
#pragma unroll
            for (int r = 0; r < 4; r++)
#pragma unroll
                for (int s = 0; s < 4; s++) acc[r][s] += a[r] * bv[s];
        }
        __syncthreads();
    }
#pragma unroll
    for (int r = 0; r < 4; r++) {
        float bv = bias[o0 + ty * 4 + r];
#pragma unroll
        for (int s = 0; s < 4; s++) Ts[tx * 4 + s][ty * 4 + r] = acc[r][s] + bv;
    }
    __syncthreads();
    int sec = o0 >> 8;                  // 0=q, 1=k, 2=v
    int h0 = (o0 & 255) >> 5;
    if (sec == 0) {
        int tl_ = tid >> 2, quad = tid & 3;
#pragma unroll
        for (int k4 = 0; k4 < 4; k4++) {
            int ol = quad * 16 + k4 * 4;
            int head = h0 + (ol >> 5);
            int d = ol & 31;
            float4 v = *(const float4*)&Ts[tl_][ol];
            *(float4*)&g_qt[(((size_t)b * NH + head) * TT + i0 + tl_) * 32 + d] = v;
        }
    } else if (sec == 1) {
#pragma unroll
        for (int wI = 0; wI < 8; wI++) {
            int idx = tid + 256 * wI;
            int hh = idx >> 10, tl = (idx >> 4) & 63, dp = idx & 15;
            float xv = Ts[tl][hh * 32 + 2 * dp], yv = Ts[tl][hh * 32 + 2 * dp + 1];
            unsigned hi, lo; split_pair(xv, yv, hi, lo);
            size_t a = (((size_t)b * NH + h0 + hh) * TT + i0 + tl) * 16 + dp;
            g_kh[a] = hi; g_kl[a] = lo;
        }
    } else {
#pragma unroll
        for (int wI = 0; wI < 8; wI++) {
            int idx = tid + 256 * wI;
            int hh = idx >> 10, dd = (idx >> 5) & 31, jp = idx & 31;
            float xv = Ts[2 * jp][hh * 32 + dd], yv = Ts[2 * jp + 1][hh * 32 + dd];
            unsigned hi, lo; split_pair(xv, yv, hi, lo);
            size_t a = (((size_t)b * NH + h0 + hh) * 32 + dd) * 288 + (i0 >> 1) + jp;
            g_vh[a] = hi; g_vl[a] = lo;
        }
    }
}

// ---------- kE ----------
__global__ __launch_bounds__(256) void kE_gemm() {
    __shared__ float Qs[64][36];
    __shared__ float Rs[48][36];
    int bn = blockIdx.y;
    int iu0 = blockIdx.x * 64;
    int n = bn & 7;
    int tid = threadIdx.x;
    const float* qsrc = g_qt + ((size_t)bn * TT + iu0) * 32;
    for (int idx = tid; idx < 64 * 32; idx += 256) Qs[idx >> 5][idx & 31] = qsrc[idx];
    for (int idx = tid; idx < 48 * 32; idx += 256) {
        int r = idx >> 5, d = idx & 31;
        Rs[r][d] = (r < 47) ? g_R[(n * 47 + r) * 32 + d] : 0.f;
    }
    __syncthreads();
    int tl = tid & 15, tiu = tid >> 4;
    float acc[4][3] = {};
#pragma unroll
    for (int d4 = 0; d4 < 8; d4++) {
        float4 q4[4], r4[3];
#pragma unroll
        for (int r = 0; r < 4; r++) q4[r] = *(const float4*)&Qs[tiu * 4 + r][d4 * 4];
#pragma unroll
        for (int j = 0; j < 3; j++) r4[j] = *(const float4*)&Rs[tl * 3 + j][d4 * 4];
#pragma unroll
        for (int r = 0; r < 4; r++)
#pragma unroll
            for (int j = 0; j < 3; j++)
                acc[r][j] += q4[r].x * r4[j].x + q4[r].y * r4[j].y +
                             q4[r].z * r4[j].z + q4[r].w * r4[j].w;
    }
    float* ep = g_E + ((size_t)bn * TT + iu0) * 48;
#pragma unroll
    for (int r = 0; r < 4; r++)
#pragma unroll
        for (int j = 0; j < 3; j++)
            ep[(tiu * 4 + r) * 48 + tl * 3 + j] = acc[r][j];
}

// ---------- k3: fused attention via bf16-split mma, 2 CTAs/SM ----------
__global__ __launch_bounds__(256, 2) void k3_attn() {
    extern __shared__ float sm[];
    float* z_s  = sm;            // [8][32][ZS] 4352 floats
    float* A_s  = sm + 4352;     // [8][16][25] 3200
    float* bd_s = sm + 7552;     // [8][16][24] 3072
    int b = blockIdx.y, i0 = blockIdx.x * 16;
    int tid = threadIdx.x, warp = tid >> 5, lane = tid & 31;
    int n = warp, bn = b * NH + n;
    int qr = lane >> 2, qc = lane & 3;

    for (int idx = tid; idx < 8 * 16 * 24; idx += 256) {
        int nn = idx / 384, r = idx % 384, ii = r / 24, c = r % 24;
        int ig = i0 + ii;
        int diff = c - ig;
        int fl = (diff >= 0) ? 0 : -((-diff + 47) / 48);
        int l = diff - 48 * fl;
        int iu = 12 + ig + fl;
        bd_s[idx] = l ? g_E[(((size_t)b * NH + nn) * TT + iu) * 48 + (l - 1)] : 0.f;
    }
    for (int idx = tid; idx < 8 * 16 * 25; idx += 256) A_s[idx] = 0.f;

    // q A-fragments (hi/lo), loaded once
    unsigned qh[2][4], ql[2][4];
#pragma unroll
    for (int kk = 0; kk < 2; kk++)
#pragma unroll
        for (int r = 0; r < 4; r++) {
            int row = i0 + qr + (r & 1) * 8;
            int col = 16 * kk + 2 * qc + (r >> 1) * 8;
            float2 v = *(const float2*)&g_qt[((size_t)bn * TT + row) * 32 + col];
            split_pair(v.x, v.y, qh[kk][r], ql[kk][r]);
        }

    // hoisted 32-bit-indexed base pointers
    const unsigned* khb = g_kh + (size_t)bn * TT * 16;
    const unsigned* klb = g_kl + (size_t)bn * TT * 16;
    const unsigned* vhb = g_vh + (size_t)bn * 32 * 288;
    const unsigned* vlb = g_vl + (size_t)bn * 32 * 288;

    float oacc[4][4];
#pragma unroll
    for (int df = 0; df < 4; df++)
#pragma unroll
        for (int r = 0; r < 4; r++) oacc[df][r] = 0.f;
    __syncthreads();

    for (int jt = 0; jt < TT; jt += 32) {
        int jtc = jt % 24;
        // ---- logits via mma ----
#pragma unroll
        for (int jf = 0; jf < 4; jf++) {
            float z[4] = {0.f, 0.f, 0.f, 0.f};
#pragma unroll
            for (int kk = 0; kk < 2; kk++) {
                unsigned base = (unsigned)(jt + 8 * jf + qr) * 16u + qc + 8 * kk;
                unsigned bh[2] = {khb[base], khb[base + 4]};
                unsigned bl[2] = {klb[base], klb[base + 4]};
                mma_bf16(z, qh[kk], bh);
                mma_bf16(z, qh[kk], bl);
                mma_bf16(z, ql[kk], bh);
            }
            int jl0 = 8 * jf + 2 * qc;
            int c0 = jtc + jl0;     if (c0 >= 24) c0 -= 24; if (c0 >= 24) c0 -= 24;
            int c1 = jtc + jl0 + 1; if (c1 >= 24) c1 -= 24; if (c1 >= 24) c1 -= 24;
            z[0] += bd_s[(n * 16 + qr) * 24 + c0];
            z[1] += bd_s[(n * 16 + qr) * 24 + c1];
            z[2] += bd_s[(n * 16 + qr + 8) * 24 + c0];
            z[3] += bd_s[(n * 16 + qr + 8) * 24 + c1];
            z_s[(n * 32 + jl0) * ZS + qr]         = z[0];
            z_s[(n * 32 + jl0 + 1) * ZS + qr]     = z[1];
            z_s[(n * 32 + jl0) * ZS + qr + 8]     = z[2];
            z_s[(n * 32 + jl0 + 1) * ZS + qr + 8] = z[3];
        }
        __syncthreads();
        // ---- softmax over heads at each (i,j) ----
        {
            int j = tid & 31, ibase = tid >> 5;
#pragma unroll
            for (int p = 0; p < 2; p++) {
                int i = ibase + 8 * p;
                float zz[8];
#pragma unroll
                for (int m = 0; m < 8; m++) zz[m] = z_s[(m * 32 + j) * ZS + i] * QSCALE;
                float mx = zz[0];
#pragma unroll
                for (int m = 1; m < 8; m++) mx = fmaxf(mx, zz[m]);
                float e[8], s = 0.f;
#pragma unroll
                for (int m = 0; m < 8; m++) { e[m] = __expf(zz[m] - mx); s += e[m]; }
                float inv = 1.f / s;
#pragma unroll
                for (int m = 0; m < 8; m++) z_s[(m * 32 + j) * ZS + i] = e[m] * inv;
            }
        }
        __syncthreads();
        // ---- A-sums: owner RMW per head-warp ----
        {
            int c = (jt + lane) % 24;
            if (lane < 24) {
#pragma unroll
                for (int ii = 0; ii < 16; ii++)
                    A_s[(n * 16 + ii) * 25 + c] += z_s[(n * 32 + lane) * ZS + ii];
            }
            __syncwarp();
            if (lane >= 24) {
#pragma unroll
                for (int ii = 0; ii < 16; ii++)
                    A_s[(n * 16 + ii) * 25 + c] += z_s[(n * 32 + lane) * ZS + ii];
            }
        }
        // ---- attn @ v via mma ----
        unsigned ah[2][4], al[2][4];
#pragma unroll
        for (int kk = 0; kk < 2; kk++)
#pragma unroll
            for (int r = 0; r < 4; r++) {
                int jb = 16 * kk + 2 * qc + (r >> 1) * 8;
                int ir = qr + (r & 1) * 8;
                float xv = z_s[(n * 32 + jb) * ZS + ir];
                float yv = z_s[(n * 32 + jb + 1) * ZS + ir];
                split_pair(xv, yv, ah[kk][r], al[kk][r]);
            }
#pragma unroll
        for (int df = 0; df < 4; df++) {
#pragma unroll
            for (int kk = 0; kk < 2; kk++) {
                unsigned base = (unsigned)(qr + 8 * df) * 288u + (jt >> 1) + qc + 8 * kk;
                unsigned bh[2] = {vhb[base], vhb[base + 4]};
                unsigned bl[2] = {vlb[base], vlb[base + 4]};
                mma_bf16(oacc[df], ah[kk], bh);
                mma_bf16(oacc[df], ah[kk], bl);
                mma_bf16(oacc[df], al[kk], bh);
            }
        }
        __syncthreads();
    }
    // ---- epilogue: positional-value term + store ----
#pragma unroll
    for (int df = 0; df < 4; df++)
#pragma unroll
        for (int r = 0; r < 4; r++) {
            int ii = qr + (r >> 1) * 8;
            int d  = 8 * df + 2 * qc + (r & 1);
            int ig = i0 + ii;
            float o2 = 0.f;
#pragma unroll
            for (int c = 0; c < 24; c++) {
                int m = (c - ig) % 48; if (m < 0) m += 48;
                o2 += A_s[(n * 16 + ii) * 25 + c] * g_P[m * 256 + n * 32 + d];
            }
            g_att[((size_t)b * TT + ig) * CCH + n * 32 + d] = oacc[df][r] + o2;
        }
}

// ---------- k4 ----------
__global__ __launch_bounds__(256) void k4_fc(const float* __restrict__ x,
                                             const float* __restrict__ w,
                                             const float* __restrict__ bias) {
    int b = blockIdx.z, o0 = blockIdx.y * 64, i0 = blockIdx.x * 64;
    __shared__ float As[16][68], Bs[16][68];
    float acc[4][4] = {};
    int tid = threadIdx.x, tx = tid % 16, ty = tid / 16;
    const float* att = g_att + (size_t)b * TT * CCH;
    for (int c0 = 0; c0 < 256; c0 += 16) {
        int row = tid >> 2, cc = (tid & 3) * 4;
        float4 wv = *(const float4*)&w[(o0 + row) * 256 + c0 + cc];
        As[cc + 0][row] = wv.x; As[cc + 1][row] = wv.y;
        As[cc + 2][row] = wv.z; As[cc + 3][row] = wv.w;
        float4 av = *(const float4*)&att[(i0 + row) * 256 + c0 + cc];
        Bs[cc + 0][row] = av.x; Bs[cc + 1][row] = av.y;
        Bs[cc + 2][row] = av.z; Bs[cc + 3][row] = av.w;
        __syncthreads();
#pragma unroll
        for (int kk = 0; kk < 16; kk++) {
            float a[4], bv[4];
            *(float4*)a  = *(const float4*)&As[kk][ty * 4];
            *(float4*)bv = *(const float4*)&Bs[kk][tx * 4];
#pragma unroll
            for (int r = 0; r < 4; r++)
#pragma unroll
                for (int s = 0; s < 4; s++) acc[r][s] += a[r] * bv[s];
        }
        __syncthreads();
    }
#pragma unroll
    for (int r = 0; r < 4; r++) {
        int o = o0 + ty * 4 + r;
        float bv = bias[o];
        float4 xv = *(const float4*)&x[((size_t)b * CCH + o) * TT + i0 + tx * 4];
        *(float4*)&g_y[((size_t)b * CCH + o) * TT + i0 + tx * 4] =
            make_float4(acc[r][0] + bv + xv.x, acc[r][1] + bv + xv.y,
                        acc[r][2] + bv + xv.z, acc[r][3] + bv + xv.w);
    }
}

__global__ void k5_gnstats() {
    int bid = blockIdx.x, b = bid >> 4, g = bid & 15;
    const float* yp = g_y + ((size_t)(b * CCH + g * 16)) * TT;
    int tid = threadIdx.x;
    float s = 0.f, sq = 0.f;
    for (int idx = tid; idx < 16 * TT; idx += 256) { float v = yp[idx]; s += v; sq += v * v; }
#pragma unroll
    for (int off = 16; off > 0; off >>= 1) {
        s  += __shfl_down_sync(0xffffffffu, s, off);
        sq += __shfl_down_sync(0xffffffffu, sq, off);
    }
    __shared__ float rs[8], rq[8];
    if ((tid & 31) == 0) { rs[tid >> 5] = s; rq[tid >> 5] = sq; }
    __syncthreads();
    if (tid == 0) {
        float S = 0.f, Q = 0.f;
#pragma unroll
        for (int w = 0; w < 8; w++) { S += rs[w]; Q += rq[w]; }
        float mu = S / 9216.f;
        float var = Q / 9216.f - mu * mu;
        g_mu[bid] = mu;
        g_rstd[bid] = rsqrtf(var + GN_EPS);
    }
}

__global__ void k6_gnapply(float* __restrict__ out, const float* __restrict__ gw,
                           const float* __restrict__ gb) {
    int idx = blockIdx.x * 256 + threadIdx.x;
    int o = (idx / TT) & 255;
    int b = idx / (TT * CCH);
    float mu = g_mu[b * 16 + (o >> 4)], rstd = g_rstd[b * 16 + (o >> 4)];
    out[idx] = (g_y[idx] - mu) * rstd * gw[o] + gb[o];
}

extern "C" void kernel_launch(void* const* d_in, const int* in_sizes, int n_in,
                              void* d_out, int out_size) {
    const float* x     = (const float*)d_in[0];
    const float* qkv_w = (const float*)d_in[1];
    const float* qkv_b = (const float*)d_in[2];
    const float* rh_k  = (const float*)d_in[3];
    const float* rw_k  = (const float*)d_in[4];
    const float* rh_v  = (const float*)d_in[5];
    const float* rw_v  = (const float*)d_in[6];
    const float* fc_w  = (const float*)d_in[7];
    const float* fc_b  = (const float*)d_in[8];
    const float* gn_w  = (const float*)d_in[9];
    const float* gn_b  = (const float*)d_in[10];
    float* out = (float*)d_out;

    cudaFuncSetAttribute(k3_attn, cudaFuncAttributeMaxDynamicSharedMemorySize, 42496);

    k0_prep<<<95, 256>>>(rh_v, rw_v, rh_k, rw_k);
    k1_qkv<<<dim3(9, 12, BB), 256>>>(x, qkv_w, qkv_b);
    kE_gemm<<<dim3(9, 128), 256>>>();
    k3_attn<<<dim3(36, BB), 256, 42496>>>();
    k4_fc<<<dim3(9, 4, BB), 256>>>(x, fc_w, fc_b);
    k5_gnstats<<<256, 256>>>();
    k6_gnapply<<<9216, 256>>>(out, gn_w, gn_b);
}

// round 10
// speedup vs baseline: 1.5054x; 1.0805x over previous
#include <cuda_runtime.h>
#include <cuda_bf16.h>
#include <math.h>

#define BB 16
#define CCH 256
#define TT 576
#define NH 8
#define QSCALE 0.17677669529663687f
#define GN_EPS 1e-5f
#define ZS 17

__device__ float g_qt[BB * NH * TT * 32];
__device__ unsigned g_kh[BB * NH * TT * 16];   // bf16x2 d-pairs, [bn][t][dp]
__device__ unsigned g_kl[BB * NH * TT * 16];
__device__ unsigned g_vh[BB * NH * 32 * 288];  // bf16x2 j-pairs, [bn][d][jp]
__device__ unsigned g_vl[BB * NH * 32 * 288];
__device__ float g_E[BB * NH * TT * 48];
__device__ float g_P[48 * 256];
__device__ float g_R[NH * 47 * 32];
__device__ float g_att[BB * TT * CCH];
__device__ float g_y[BB * CCH * TT];
__device__ float g_mu[BB * 16];
__device__ float g_rstd[BB * 16];

__device__ __forceinline__ unsigned pack_bf16(float x, float y) {
    __nv_bfloat162 t = __floats2bfloat162_rn(x, y);
    return *reinterpret_cast<unsigned*>(&t);
}
__device__ __forceinline__ void split_pair(float x, float y, unsigned& hi, unsigned& lo) {
    float xh = __bfloat162float(__float2bfloat16_rn(x));
    float yh = __bfloat162float(__float2bfloat16_rn(y));
    hi = pack_bf16(xh, yh);
    lo = pack_bf16(x - xh, y - yh);
}
__device__ __forceinline__ void mma_bf16(float* d, const unsigned* a, const unsigned* b) {
    asm volatile("mma.sync.aligned.m16n8k16.row.col.f32.bf16.bf16.f32 "
                 "{%0,%1,%2,%3},{%4,%5,%6,%7},{%8,%9},{%0,%1,%2,%3};"
                 : "+f"(d[0]), "+f"(d[1]), "+f"(d[2]), "+f"(d[3])
                 : "r"(a[0]), "r"(a[1]), "r"(a[2]), "r"(a[3]), "r"(b[0]), "r"(b[1]));
}

// ---------- k0 ----------
__global__ void k0_prep(const float* __restrict__ rh_v, const float* __restrict__ rw_v,
                        const float* __restrict__ rh_k, const float* __restrict__ rw_k) {
    int bx = blockIdx.x, tid = threadIdx.x;
    if (bx < 48) {
        int idx = bx * 256 + tid;
        int m = idx >> 8, rest = idx & 255;
        g_P[idx] = (m > 0) ? (rh_v[(m - 1) * 256 + rest] + rw_v[(m - 1) * 256 + rest]) : 0.f;
    } else {
        int l = bx - 48;
        int n = tid >> 5, d = tid & 31;
        g_R[(n * 47 + l) * 32 + d] = rh_k[(l * 8 + n) * 32 + d] + rw_k[(l * 8 + n) * 32 + d];
    }
}

// ---------- k1: qkv GEMM, epilogue emits q f32 / k,v bf16-split layouts ----------
__global__ __launch_bounds__(256) void k1_qkv(const float* __restrict__ x,
                                              const float* __restrict__ w,
                                              const float* __restrict__ bias) {
    int b = blockIdx.z, o0 = blockIdx.y * 64, i0 = blockIdx.x * 64;
    __shared__ float As[16][68], Bs[16][68];
    __shared__ float Ts[64][68];
    float acc[4][4] = {};
    int tid = threadIdx.x, tx = tid % 16, ty = tid / 16;
    const float* xb = x + (size_t)b * CCH * TT;
    for (int c0 = 0; c0 < 256; c0 += 16) {
        int row = tid >> 2, cc = (tid & 3) * 4;
        float4 wv = *(const float4*)&w[(o0 + row) * 256 + c0 + cc];
        As[cc + 0][row] = wv.x; As[cc + 1][row] = wv.y;
        As[cc + 2][row] = wv.z; As[cc + 3][row] = wv.w;
        int cr = tid >> 4, i4 = (tid & 15) * 4;
        *(float4*)&Bs[cr][i4] = *(const float4*)&xb[(c0 + cr) * TT + i0 + i4];
        __syncthreads();
#pragma unroll
        for (int kk = 0; kk < 16; kk++) {
            float a[4], bv[4];
            *(float4*)a  = *(const float4*)&As[kk][ty * 4];
            *(float4*)bv = *(const float4*)&Bs[kk][tx * 4];
#pragma unroll
            for (int r = 0; r < 4; r++)
#pragma unroll
                for (int s = 0; s < 4; s++) acc[r][s] += a[r] * bv[s];
        }
        __syncthreads();
    }
#pragma unroll
    for (int r = 0; r < 4; r++) {
        float bv = bias[o0 + ty * 4 + r];
#pragma unroll
        for (int s = 0; s < 4; s++) Ts[tx * 4 + s][ty * 4 + r] = acc[r][s] + bv;
    }
    __syncthreads();
    int sec = o0 >> 8;                  // 0=q, 1=k, 2=v
    int h0 = (o0 & 255) >> 5;
    if (sec == 0) {
        int tl_ = tid >> 2, quad = tid & 3;
#pragma unroll
        for (int k4 = 0; k4 < 4; k4++) {
            int ol = quad * 16 + k4 * 4;
            int head = h0 + (ol >> 5);
            int d = ol & 31;
            float4 v = *(const float4*)&Ts[tl_][ol];
            *(float4*)&g_qt[(((size_t)b * NH + head) * TT + i0 + tl_) * 32 + d] = v;
        }
    } else if (sec == 1) {
#pragma unroll
        for (int wI = 0; wI < 8; wI++) {
            int idx = tid + 256 * wI;
            int hh = idx >> 10, tl = (idx >> 4) & 63, dp = idx & 15;
            float xv = Ts[tl][hh * 32 + 2 * dp], yv = Ts[tl][hh * 32 + 2 * dp + 1];
            unsigned hi, lo; split_pair(xv, yv, hi, lo);
            size_t a = (((size_t)b * NH + h0 + hh) * TT + i0 + tl) * 16 + dp;
            g_kh[a] = hi; g_kl[a] = lo;
        }
    } else {
#pragma unroll
        for (int wI = 0; wI < 8; wI++) {
            int idx = tid + 256 * wI;
            int hh = idx >> 10, dd = (idx >> 5) & 31, jp = idx & 31;
            float xv = Ts[2 * jp][hh * 32 + dd], yv = Ts[2 * jp + 1][hh * 32 + dd];
            unsigned hi, lo; split_pair(xv, yv, hi, lo);
            size_t a = (((size_t)b * NH + h0 + hh) * 32 + dd) * 288 + (i0 >> 1) + jp;
            g_vh[a] = hi; g_vl[a] = lo;
        }
    }
}

// ---------- kE ----------
__global__ __launch_bounds__(256) void kE_gemm() {
    __shared__ float Qs[64][36];
    __shared__ float Rs[48][36];
    int bn = blockIdx.y;
    int iu0 = blockIdx.x * 64;
    int n = bn & 7;
    int tid = threadIdx.x;
    const float* qsrc = g_qt + ((size_t)bn * TT + iu0) * 32;
    for (int idx = tid; idx < 64 * 32; idx += 256) Qs[idx >> 5][idx & 31] = qsrc[idx];
    for (int idx = tid; idx < 48 * 32; idx += 256) {
        int r = idx >> 5, d = idx & 31;
        Rs[r][d] = (r < 47) ? g_R[(n * 47 + r) * 32 + d] : 0.f;
    }
    __syncthreads();
    int tl = tid & 15, tiu = tid >> 4;
    float acc[4][3] = {};
#pragma unroll
    for (int d4 = 0; d4 < 8; d4++) {
        float4 q4[4], r4[3];
#pragma unroll
        for (int r = 0; r < 4; r++) q4[r] = *(const float4*)&Qs[tiu * 4 + r][d4 * 4];
#pragma unroll
        for (int j = 0; j < 3; j++) r4[j] = *(const float4*)&Rs[tl * 3 + j][d4 * 4];
#pragma unroll
        for (int r = 0; r < 4; r++)
#pragma unroll
            for (int j = 0; j < 3; j++)
                acc[r][j] += q4[r].x * r4[j].x + q4[r].y * r4[j].y +
                             q4[r].z * r4[j].z + q4[r].w * r4[j].w;
    }
    float* ep = g_E + ((size_t)bn * TT + iu0) * 48;
#pragma unroll
    for (int r = 0; r < 4; r++)
#pragma unroll
        for (int j = 0; j < 3; j++)
            ep[(tiu * 4 + r) * 48 + tl * 3 + j] = acc[r][j];
}

// ---------- k3: fused attention via bf16-split mma; A-sums on tensor pipe ----------
__global__ __launch_bounds__(256, 2) void k3_attn() {
    extern __shared__ float sm[];
    float* z_s  = sm;            // [8][32][ZS] 4352 floats
    float* A_s  = sm + 4352;     // [8][16][25] 3200
    float* bd_s = sm + 7552;     // [8][16][24] 3072
    int b = blockIdx.y, i0 = blockIdx.x * 16;
    int tid = threadIdx.x, warp = tid >> 5, lane = tid & 31;
    int n = warp, bn = b * NH + n;
    int qr = lane >> 2, qc = lane & 3;

    for (int idx = tid; idx < 8 * 16 * 24; idx += 256) {
        int nn = idx / 384, r = idx % 384, ii = r / 24, c = r % 24;
        int ig = i0 + ii;
        int diff = c - ig;
        int fl = (diff >= 0) ? 0 : -((-diff + 47) / 48);
        int l = diff - 48 * fl;
        int iu = 12 + ig + fl;
        bd_s[idx] = l ? g_E[(((size_t)b * NH + nn) * TT + iu) * 48 + (l - 1)] : 0.f;
    }

    // q A-fragments (hi/lo), loaded once
    unsigned qh[2][4], ql[2][4];
#pragma unroll
    for (int kk = 0; kk < 2; kk++)
#pragma unroll
        for (int r = 0; r < 4; r++) {
            int row = i0 + qr + (r & 1) * 8;
            int col = 16 * kk + 2 * qc + (r >> 1) * 8;
            float2 v = *(const float2*)&g_qt[((size_t)bn * TT + row) * 32 + col];
            split_pair(v.x, v.y, qh[kk][r], ql[kk][r]);
        }

    const unsigned* khb = g_kh + (size_t)bn * TT * 16;
    const unsigned* klb = g_kl + (size_t)bn * TT * 16;
    const unsigned* vhb = g_vh + (size_t)bn * 32 * 288;
    const unsigned* vlb = g_vl + (size_t)bn * 32 * 288;

    float oacc[4][4];
#pragma unroll
    for (int df = 0; df < 4; df++)
#pragma unroll
        for (int r = 0; r < 4; r++) oacc[df][r] = 0.f;
    float cA[3][4];
#pragma unroll
    for (int nf = 0; nf < 3; nf++)
#pragma unroll
        for (int r = 0; r < 4; r++) cA[nf][r] = 0.f;
    __syncthreads();

    for (int jt = 0; jt < TT; jt += 32) {
        int jtc = jt % 24;
        // ---- logits via mma ----
#pragma unroll
        for (int jf = 0; jf < 4; jf++) {
            float z[4] = {0.f, 0.f, 0.f, 0.f};
#pragma unroll
            for (int kk = 0; kk < 2; kk++) {
                unsigned base = (unsigned)(jt + 8 * jf + qr) * 16u + qc + 8 * kk;
                unsigned bh[2] = {khb[base], khb[base + 4]};
                unsigned bl[2] = {klb[base], klb[base + 4]};
                mma_bf16(z, qh[kk], bh);
                mma_bf16(z, qh[kk], bl);
                mma_bf16(z, ql[kk], bh);
            }
            int jl0 = 8 * jf + 2 * qc;
            int c0 = jtc + jl0;     if (c0 >= 24) c0 -= 24; if (c0 >= 24) c0 -= 24;
            int c1 = jtc + jl0 + 1; if (c1 >= 24) c1 -= 24; if (c1 >= 24) c1 -= 24;
            z[0] += bd_s[(n * 16 + qr) * 24 + c0];
            z[1] += bd_s[(n * 16 + qr) * 24 + c1];
            z[2] += bd_s[(n * 16 + qr + 8) * 24 + c0];
            z[3] += bd_s[(n * 16 + qr + 8) * 24 + c1];
            z_s[(n * 32 + jl0) * ZS + qr]         = z[0];
            z_s[(n * 32 + jl0 + 1) * ZS + qr]     = z[1];
            z_s[(n * 32 + jl0) * ZS + qr + 8]     = z[2];
            z_s[(n * 32 + jl0 + 1) * ZS + qr + 8] = z[3];
        }
        __syncthreads();
        // ---- softmax over heads at each (i,j) ----
        {
            int j = tid & 31, ibase = tid >> 5;
#pragma unroll
            for (int p = 0; p < 2; p++) {
                int i = ibase + 8 * p;
                float zz[8];
#pragma unroll
                for (int m = 0; m < 8; m++) zz[m] = z_s[(m * 32 + j) * ZS + i] * QSCALE;
                float mx = zz[0];
#pragma unroll
                for (int m = 1; m < 8; m++) mx = fmaxf(mx, zz[m]);
                float e[8], s = 0.f;
#pragma unroll
                for (int m = 0; m < 8; m++) { e[m] = __expf(zz[m] - mx); s += e[m]; }
                float inv = 1.f / s;
#pragma unroll
                for (int m = 0; m < 8; m++) z_s[(m * 32 + j) * ZS + i] = e[m] * inv;
            }
        }
        __syncthreads();
        // ---- attn fragments (hi/lo) ----
        unsigned ah[2][4], al[2][4];
#pragma unroll
        for (int kk = 0; kk < 2; kk++)
#pragma unroll
            for (int r = 0; r < 4; r++) {
                int jb = 16 * kk + 2 * qc + (r >> 1) * 8;
                int ir = qr + (r & 1) * 8;
                float xv = z_s[(n * 32 + jb) * ZS + ir];
                float yv = z_s[(n * 32 + jb + 1) * ZS + ir];
                split_pair(xv, yv, ah[kk][r], al[kk][r]);
            }
        // ---- A-sums via mma with 0/1 selection matrix S ----
#pragma unroll
        for (int kk = 0; kk < 2; kk++) {
            int jm0 = jtc + 16 * kk + 2 * qc; jm0 %= 24;
            int jm1 = (jm0 + 1) % 24;
            int jm8 = (jm0 + 8) % 24;
            int jm9 = (jm8 + 1) % 24;
#pragma unroll
            for (int nf = 0; nf < 3; nf++) {
                int cg = 8 * nf + qr;
                unsigned sb[2];
                sb[0] = pack_bf16(jm0 == cg ? 1.f : 0.f, jm1 == cg ? 1.f : 0.f);
                sb[1] = pack_bf16(jm8 == cg ? 1.f : 0.f, jm9 == cg ? 1.f : 0.f);
                mma_bf16(cA[nf], ah[kk], sb);
                mma_bf16(cA[nf], al[kk], sb);
            }
        }
        // ---- attn @ v via mma ----
#pragma unroll
        for (int df = 0; df < 4; df++) {
#pragma unroll
            for (int kk = 0; kk < 2; kk++) {
                unsigned base = (unsigned)(qr + 8 * df) * 288u + (jt >> 1) + qc + 8 * kk;
                unsigned bh[2] = {vhb[base], vhb[base + 4]};
                unsigned bl[2] = {vlb[base], vlb[base + 4]};
                mma_bf16(oacc[df], ah[kk], bh);
                mma_bf16(oacc[df], ah[kk], bl);
                mma_bf16(oacc[df], al[kk], bh);
            }
        }
        __syncthreads();
    }
    // ---- write A fragments to smem once ----
#pragma unroll
    for (int nf = 0; nf < 3; nf++) {
        int cg = 8 * nf + 2 * qc;
        A_s[(n * 16 + qr) * 25 + cg]         = cA[nf][0];
        A_s[(n * 16 + qr) * 25 + cg + 1]     = cA[nf][1];
        A_s[(n * 16 + qr + 8) * 25 + cg]     = cA[nf][2];
        A_s[(n * 16 + qr + 8) * 25 + cg + 1] = cA[nf][3];
    }
    __syncwarp();
    // ---- epilogue: positional-value term + store ----
#pragma unroll
    for (int df = 0; df < 4; df++)
#pragma unroll
        for (int r = 0; r < 4; r++) {
            int ii = qr + (r >> 1) * 8;
            int d  = 8 * df + 2 * qc + (r & 1);
            int ig = i0 + ii;
            float o2 = 0.f;
#pragma unroll
            for (int c = 0; c < 24; c++) {
                int m = (c - ig) % 48; if (m < 0) m += 48;
                o2 += A_s[(n * 16 + ii) * 25 + c] * g_P[m * 256 + n * 32 + d];
            }
            g_att[((size_t)b * TT + ig) * CCH + n * 32 + d] = oacc[df][r] + o2;
        }
}

// ---------- k4 ----------
__global__ __launch_bounds__(256) void k4_fc(const float* __restrict__ x,
                                             const float* __restrict__ w,
                                             const float* __restrict__ bias) {
    int b = blockIdx.z, o0 = blockIdx.y * 64, i0 = blockIdx.x * 64;
    __shared__ float As[16][68], Bs[16][68];
    float acc[4][4] = {};
    int tid = threadIdx.x, tx = tid % 16, ty = tid / 16;
    const float* att = g_att + (size_t)b * TT * CCH;
    for (int c0 = 0; c0 < 256; c0 += 16) {
        int row = tid >> 2, cc = (tid & 3) * 4;
        float4 wv = *(const float4*)&w[(o0 + row) * 256 + c0 + cc];
        As[cc + 0][row] = wv.x; As[cc + 1][row] = wv.y;
        As[cc + 2][row] = wv.z; As[cc + 3][row] = wv.w;
        float4 av = *(const float4*)&att[(i0 + row) * 256 + c0 + cc];
        Bs[cc + 0][row] = av.x; Bs[cc + 1][row] = av.y;
        Bs[cc + 2][row] = av.z; Bs[cc + 3][row] = av.w;
        __syncthreads();
#pragma unroll
        for (int kk = 0; kk < 16; kk++) {
            float a[4], bv[4];
            *(float4*)a  = *(const float4*)&As[kk][ty * 4];
            *(float4*)bv = *(const float4*)&Bs[kk][tx * 4];
#pragma unroll
            for (int r = 0; r < 4; r++)
#pragma unroll
                for (int s = 0; s < 4; s++) acc[r][s] += a[r] * bv[s];
        }
        __syncthreads();
    }
#pragma unroll
    for (int r = 0; r < 4; r++) {
        int o = o0 + ty * 4 + r;
        float bv = bias[o];
        float4 xv = *(const float4*)&x[((size_t)b * CCH + o) * TT + i0 + tx * 4];
        *(float4*)&g_y[((size_t)b * CCH + o) * TT + i0 + tx * 4] =
            make_float4(acc[r][0] + bv + xv.x, acc[r][1] + bv + xv.y,
                        acc[r][2] + bv + xv.z, acc[r][3] + bv + xv.w);
    }
}

__global__ void k5_gnstats() {
    int bid = blockIdx.x, b = bid >> 4, g = bid & 15;
    const float* yp = g_y + ((size_t)(b * CCH + g * 16)) * TT;
    int tid = threadIdx.x;
    float s = 0.f, sq = 0.f;
    for (int idx = tid; idx < 16 * TT; idx += 256) { float v = yp[idx]; s += v; sq += v * v; }
#pragma unroll
    for (int off = 16; off > 0; off >>= 1) {
        s  += __shfl_down_sync(0xffffffffu, s, off);
        sq += __shfl_down_sync(0xffffffffu, sq, off);
    }
    __shared__ float rs[8], rq[8];
    if ((tid & 31) == 0) { rs[tid >> 5] = s; rq[tid >> 5] = sq; }
    __syncthreads();
    if (tid == 0) {
        float S = 0.f, Q = 0.f;
#pragma unroll
        for (int w = 0; w < 8; w++) { S += rs[w]; Q += rq[w]; }
        float mu = S / 9216.f;
        float var = Q / 9216.f - mu * mu;
        g_mu[bid] = mu;
        g_rstd[bid] = rsqrtf(var + GN_EPS);
    }
}

__global__ void k6_gnapply(float* __restrict__ out, const float* __restrict__ gw,
                           const float* __restrict__ gb) {
    int idx = blockIdx.x * 256 + threadIdx.x;
    int o = (idx / TT) & 255;
    int b = idx / (TT * CCH);
    float mu = g_mu[b * 16 + (o >> 4)], rstd = g_rstd[b * 16 + (o >> 4)];
    out[idx] = (g_y[idx] - mu) * rstd * gw[o] + gb[o];
}

extern "C" void kernel_launch(void* const* d_in, const int* in_sizes, int n_in,
                              void* d_out, int out_size) {
    const float* x     = (const float*)d_in[0];
    const float* qkv_w = (const float*)d_in[1];
    const float* qkv_b = (const float*)d_in[2];
    const float* rh_k  = (const float*)d_in[3];
    const float* rw_k  = (const float*)d_in[4];
    const float* rh_v  = (const float*)d_in[5];
    const float* rw_v  = (const float*)d_in[6];
    const float* fc_w  = (const float*)d_in[7];
    const float* fc_b  = (const float*)d_in[8];
    const float* gn_w  = (const float*)d_in[9];
    const float* gn_b  = (const float*)d_in[10];
    float* out = (float*)d_out;

    cudaFuncSetAttribute(k3_attn, cudaFuncAttributeMaxDynamicSharedMemorySize, 42496);

    k0_prep<<<95, 256>>>(rh_v, rw_v, rh_k, rw_k);
    k1_qkv<<<dim3(9, 12, BB), 256>>>(x, qkv_w, qkv_b);
    kE_gemm<<<dim3(9, 128), 256>>>();
    k3_attn<<<dim3(36, BB), 256, 42496>>>();
    k4_fc<<<dim3(9, 4, BB), 256>>>(x, fc_w, fc_b);
    k5_gnstats<<<256, 256>>>();
    k6_gnapply<<<9216, 256>>>(out, gn_w, gn_b);
}

// round 11
// speedup vs baseline: 1.5943x; 1.0590x over previous
#include <cuda_runtime.h>
#include <cuda_bf16.h>
#include <math.h>

#define BB 16
#define CCH 256
#define TT 576
#define NH 8
#define QSCALE 0.17677669529663687f
#define GN_EPS 1e-5f
#define ZS 17

__device__ float g_qt[BB * NH * TT * 32];
__device__ uint2 g_k[BB * NH * TT * 16];      // (hi,lo) bf16x2 d-pairs, [bn][t][dp]
__device__ uint2 g_v[BB * NH * 32 * 288];     // (hi,lo) bf16x2 j-pairs, [bn][d][jp]
__device__ float g_E[BB * NH * TT * 48];
__device__ float g_P[48 * 256];
__device__ float g_R[NH * 47 * 32];
__device__ float g_att[BB * TT * CCH];
__device__ float g_y[BB * CCH * TT];
__device__ float g_mu[BB * 16];
__device__ float g_rstd[BB * 16];

__device__ __forceinline__ unsigned pack_bf16(float x, float y) {
    __nv_bfloat162 t = __floats2bfloat162_rn(x, y);
    return *reinterpret_cast<unsigned*>(&t);
}
__device__ __forceinline__ void split_pair(float x, float y, unsigned& hi, unsigned& lo) {
    float xh = __bfloat162float(__float2bfloat16_rn(x));
    float yh = __bfloat162float(__float2bfloat16_rn(y));
    hi = pack_bf16(xh, yh);
    lo = pack_bf16(x - xh, y - yh);
}
__device__ __forceinline__ void mma_bf16(float* d, const unsigned* a, const unsigned* b) {
    asm volatile("mma.sync.aligned.m16n8k16.row.col.f32.bf16.bf16.f32 "
                 "{%0,%1,%2,%3},{%4,%5,%6,%7},{%8,%9},{%0,%1,%2,%3};"
                 : "+f"(d[0]), "+f"(d[1]), "+f"(d[2]), "+f"(d[3])
                 : "r"(a[0]), "r"(a[1]), "r"(a[2]), "r"(a[3]), "r"(b[0]), "r"(b[1]));
}

// ---------- k0 ----------
__global__ void k0_prep(const float* __restrict__ rh_v, const float* __restrict__ rw_v,
                        const float* __restrict__ rh_k, const float* __restrict__ rw_k) {
    int bx = blockIdx.x, tid = threadIdx.x;
    if (bx < 48) {
        int idx = bx * 256 + tid;
        int m = idx >> 8, rest = idx & 255;
        g_P[idx] = (m > 0) ? (rh_v[(m - 1) * 256 + rest] + rw_v[(m - 1) * 256 + rest]) : 0.f;
    } else {
        int l = bx - 48;
        int n = tid >> 5, d = tid & 31;
        g_R[(n * 47 + l) * 32 + d] = rh_k[(l * 8 + n) * 32 + d] + rw_k[(l * 8 + n) * 32 + d];
    }
}

// ---------- k1: qkv GEMM, epilogue emits q f32 / k,v interleaved bf16-split ----------
__global__ __launch_bounds__(256) void k1_qkv(const float* __restrict__ x,
                                              const float* __restrict__ w,
                                              const float* __restrict__ bias) {
    int b = blockIdx.z, o0 = blockIdx.y * 64, i0 = blockIdx.x * 64;
    __shared__ float As[16][68], Bs[16][68];
    __shared__ float Ts[64][68];
    float acc[4][4] = {};
    int tid = threadIdx.x, tx = tid % 16, ty = tid / 16;
    const float* xb = x + (size_t)b * CCH * TT;
    for (int c0 = 0; c0 < 256; c0 += 16) {
        int row = tid >> 2, cc = (tid & 3) * 4;
        float4 wv = *(const float4*)&w[(o0 + row) * 256 + c0 + cc];
        As[cc + 0][row] = wv.x; As[cc + 1][row] = wv.y;
        As[cc + 2][row] = wv.z; As[cc + 3][row] = wv.w;
        int cr = tid >> 4, i4 = (tid & 15) * 4;
        *(float4*)&Bs[cr][i4] = *(const float4*)&xb[(c0 + cr) * TT + i0 + i4];
        __syncthreads();
#pragma unroll
        for (int kk = 0; kk < 16; kk++) {
            float a[4], bv[4];
            *(float4*)a  = *(const float4*)&As[kk][ty * 4];
            *(float4*)bv = *(const float4*)&Bs[kk][tx * 4];
#pragma unroll
            for (int r = 0; r < 4; r++)
#pragma unroll
                for (int s = 0; s < 4; s++) acc[r][s] += a[r] * bv[s];
        }
        __syncthreads();
    }
#pragma unroll
    for (int r = 0; r < 4; r++) {
        float bv = bias[o0 + ty * 4 + r];
#pragma unroll
        for (int s = 0; s < 4; s++) Ts[tx * 4 + s][ty * 4 + r] = acc[r][s] + bv;
    }
    __syncthreads();
    int sec = o0 >> 8;                  // 0=q, 1=k, 2=v
    int h0 = (o0 & 255) >> 5;
    if (sec == 0) {
        int tl_ = tid >> 2, quad = tid & 3;
#pragma unroll
        for (int k4 = 0; k4 < 4; k4++) {
            int ol = quad * 16 + k4 * 4;
            int head = h0 + (ol >> 5);
            int d = ol & 31;
            float4 v = *(const float4*)&Ts[tl_][ol];
            *(float4*)&g_qt[(((size_t)b * NH + head) * TT + i0 + tl_) * 32 + d] = v;
        }
    } else if (sec == 1) {
#pragma unroll
        for (int wI = 0; wI < 8; wI++) {
            int idx = tid + 256 * wI;
            int hh = idx >> 10, tl = (idx >> 4) & 63, dp = idx & 15;
            float xv = Ts[tl][hh * 32 + 2 * dp], yv = Ts[tl][hh * 32 + 2 * dp + 1];
            unsigned hi, lo; split_pair(xv, yv, hi, lo);
            size_t a = (((size_t)b * NH + h0 + hh) * TT + i0 + tl) * 16 + dp;
            g_k[a] = make_uint2(hi, lo);
        }
    } else {
#pragma unroll
        for (int wI = 0; wI < 8; wI++) {
            int idx = tid + 256 * wI;
            int hh = idx >> 10, dd = (idx >> 5) & 31, jp = idx & 31;
            float xv = Ts[2 * jp][hh * 32 + dd], yv = Ts[2 * jp + 1][hh * 32 + dd];
            unsigned hi, lo; split_pair(xv, yv, hi, lo);
            size_t a = (((size_t)b * NH + h0 + hh) * 32 + dd) * 288 + (i0 >> 1) + jp;
            g_v[a] = make_uint2(hi, lo);
        }
    }
}

// ---------- kE ----------
__global__ __launch_bounds__(256) void kE_gemm() {
    __shared__ float Qs[64][36];
    __shared__ float Rs[48][36];
    int bn = blockIdx.y;
    int iu0 = blockIdx.x * 64;
    int n = bn & 7;
    int tid = threadIdx.x;
    const float* qsrc = g_qt + ((size_t)bn * TT + iu0) * 32;
    for (int idx = tid; idx < 64 * 32; idx += 256) Qs[idx >> 5][idx & 31] = qsrc[idx];
    for (int idx = tid; idx < 48 * 32; idx += 256) {
        int r = idx >> 5, d = idx & 31;
        Rs[r][d] = (r < 47) ? g_R[(n * 47 + r) * 32 + d] : 0.f;
    }
    __syncthreads();
    int tl = tid & 15, tiu = tid >> 4;
    float acc[4][3] = {};
#pragma unroll
    for (int d4 = 0; d4 < 8; d4++) {
        float4 q4[4], r4[3];
#pragma unroll
        for (int r = 0; r < 4; r++) q4[r] = *(const float4*)&Qs[tiu * 4 + r][d4 * 4];
#pragma unroll
        for (int j = 0; j < 3; j++) r4[j] = *(const float4*)&Rs[tl * 3 + j][d4 * 4];
#pragma unroll
        for (int r = 0; r < 4; r++)
#pragma unroll
            for (int j = 0; j < 3; j++)
                acc[r][j] += q4[r].x * r4[j].x + q4[r].y * r4[j].y +
                             q4[r].z * r4[j].z + q4[r].w * r4[j].w;
    }
    float* ep = g_E + ((size_t)bn * TT + iu0) * 48;
#pragma unroll
    for (int r = 0; r < 4; r++)
#pragma unroll
        for (int j = 0; j < 3; j++)
            ep[(tiu * 4 + r) * 48 + tl * 3 + j] = acc[r][j];
}

// ---------- k3: fused attention, bf16-split mma, interleaved LDG.64 ----------
__global__ __launch_bounds__(256, 2) void k3_attn() {
    extern __shared__ float sm[];
    float* z_s  = sm;            // [8][32][ZS] 4352 floats
    float* A_s  = sm + 4352;     // [8][16][25] 3200
    float* bd_s = sm + 7552;     // [8][16][24] 3072
    int b = blockIdx.y, i0 = blockIdx.x * 16;
    int tid = threadIdx.x, warp = tid >> 5, lane = tid & 31;
    int n = warp, bn = b * NH + n;
    int qr = lane >> 2, qc = lane & 3;

    for (int idx = tid; idx < 8 * 16 * 24; idx += 256) {
        int nn = idx / 384, r = idx % 384, ii = r / 24, c = r % 24;
        int ig = i0 + ii;
        int diff = c - ig;
        int fl = (diff >= 0) ? 0 : -((-diff + 47) / 48);
        int l = diff - 48 * fl;
        int iu = 12 + ig + fl;
        bd_s[idx] = l ? g_E[(((size_t)b * NH + nn) * TT + iu) * 48 + (l - 1)] : 0.f;
    }

    // q A-fragments (hi/lo), loaded once
    unsigned qh[2][4], ql[2][4];
#pragma unroll
    for (int kk = 0; kk < 2; kk++)
#pragma unroll
        for (int r = 0; r < 4; r++) {
            int row = i0 + qr + (r & 1) * 8;
            int col = 16 * kk + 2 * qc + (r >> 1) * 8;
            float2 v = *(const float2*)&g_qt[((size_t)bn * TT + row) * 32 + col];
            split_pair(v.x, v.y, qh[kk][r], ql[kk][r]);
        }

    const uint2* kb = g_k + (size_t)bn * TT * 16;
    const uint2* vb = g_v + (size_t)bn * 32 * 288;

    float oacc[4][4];
#pragma unroll
    for (int df = 0; df < 4; df++)
#pragma unroll
        for (int r = 0; r < 4; r++) oacc[df][r] = 0.f;
    float cA[3][4];
#pragma unroll
    for (int nf = 0; nf < 3; nf++)
#pragma unroll
        for (int r = 0; r < 4; r++) cA[nf][r] = 0.f;
    __syncthreads();

    for (int jt = 0; jt < TT; jt += 32) {
        int jtc = jt % 24;
        // ---- logits via mma (LDG.64 fragments) ----
#pragma unroll
        for (int jf = 0; jf < 4; jf++) {
            float z[4] = {0.f, 0.f, 0.f, 0.f};
#pragma unroll
            for (int kk = 0; kk < 2; kk++) {
                unsigned base = (unsigned)(jt + 8 * jf + qr) * 16u + qc + 8 * kk;
                uint2 w0 = kb[base], w1 = kb[base + 4];
                unsigned bh[2] = {w0.x, w1.x};
                unsigned bl[2] = {w0.y, w1.y};
                mma_bf16(z, qh[kk], bh);
                mma_bf16(z, qh[kk], bl);
                mma_bf16(z, ql[kk], bh);
            }
            int jl0 = 8 * jf + 2 * qc;
            int c0 = jtc + jl0;     if (c0 >= 24) c0 -= 24; if (c0 >= 24) c0 -= 24;
            int c1 = jtc + jl0 + 1; if (c1 >= 24) c1 -= 24; if (c1 >= 24) c1 -= 24;
            z[0] += bd_s[(n * 16 + qr) * 24 + c0];
            z[1] += bd_s[(n * 16 + qr) * 24 + c1];
            z[2] += bd_s[(n * 16 + qr + 8) * 24 + c0];
            z[3] += bd_s[(n * 16 + qr + 8) * 24 + c1];
            z_s[(n * 32 + jl0) * ZS + qr]         = z[0];
            z_s[(n * 32 + jl0 + 1) * ZS + qr]     = z[1];
            z_s[(n * 32 + jl0) * ZS + qr + 8]     = z[2];
            z_s[(n * 32 + jl0 + 1) * ZS + qr + 8] = z[3];
        }
        __syncthreads();
        // ---- softmax over heads at each (i,j) ----
        {
            int j = tid & 31, ibase = tid >> 5;
#pragma unroll
            for (int p = 0; p < 2; p++) {
                int i = ibase + 8 * p;
                float zz[8];
#pragma unroll
                for (int m = 0; m < 8; m++) zz[m] = z_s[(m * 32 + j) * ZS + i] * QSCALE;
                float mx = zz[0];
#pragma unroll
                for (int m = 1; m < 8; m++) mx = fmaxf(mx, zz[m]);
                float e[8], s = 0.f;
#pragma unroll
                for (int m = 0; m < 8; m++) { e[m] = __expf(zz[m] - mx); s += e[m]; }
                float inv = 1.f / s;
#pragma unroll
                for (int m = 0; m < 8; m++) z_s[(m * 32 + j) * ZS + i] = e[m] * inv;
            }
        }
        __syncthreads();
        // ---- attn fragments (hi/lo) ----
        unsigned ah[2][4], al[2][4];
#pragma unroll
        for (int kk = 0; kk < 2; kk++)
#pragma unroll
            for (int r = 0; r < 4; r++) {
                int jb = 16 * kk + 2 * qc + (r >> 1) * 8;
                int ir = qr + (r & 1) * 8;
                float xv = z_s[(n * 32 + jb) * ZS + ir];
                float yv = z_s[(n * 32 + jb + 1) * ZS + ir];
                split_pair(xv, yv, ah[kk][r], al[kk][r]);
            }
        // ---- A-sums via mma with 0/1 selection matrix S ----
#pragma unroll
        for (int kk = 0; kk < 2; kk++) {
            int jm0 = jtc + 16 * kk + 2 * qc; jm0 %= 24;
            int jm1 = (jm0 + 1) % 24;
            int jm8 = (jm0 + 8) % 24;
            int jm9 = (jm8 + 1) % 24;
#pragma unroll
            for (int nf = 0; nf < 3; nf++) {
                int cg = 8 * nf + qr;
                unsigned sb[2];
                sb[0] = pack_bf16(jm0 == cg ? 1.f : 0.f, jm1 == cg ? 1.f : 0.f);
                sb[1] = pack_bf16(jm8 == cg ? 1.f : 0.f, jm9 == cg ? 1.f : 0.f);
                mma_bf16(cA[nf], ah[kk], sb);
                mma_bf16(cA[nf], al[kk], sb);
            }
        }
        // ---- attn @ v via mma (LDG.64 fragments) ----
#pragma unroll
        for (int df = 0; df < 4; df++) {
#pragma unroll
            for (int kk = 0; kk < 2; kk++) {
                unsigned base = (unsigned)(qr + 8 * df) * 288u + (jt >> 1) + qc + 8 * kk;
                uint2 w0 = vb[base], w1 = vb[base + 4];
                unsigned bh[2] = {w0.x, w1.x};
                unsigned bl[2] = {w0.y, w1.y};
                mma_bf16(oacc[df], ah[kk], bh);
                mma_bf16(oacc[df], ah[kk], bl);
                mma_bf16(oacc[df], al[kk], bh);
            }
        }
        // NOTE: no barrier here — after the post-softmax barrier, z_s rows
        // n*32+* are touched only by warp n (phase-3 reads and next-tile
        // logits writes are same-warp, program-ordered).
    }
    // ---- write A fragments to smem once ----
#pragma unroll
    for (int nf = 0; nf < 3; nf++) {
        int cg = 8 * nf + 2 * qc;
        A_s[(n * 16 + qr) * 25 + cg]         = cA[nf][0];
        A_s[(n * 16 + qr) * 25 + cg + 1]     = cA[nf][1];
        A_s[(n * 16 + qr + 8) * 25 + cg]     = cA[nf][2];
        A_s[(n * 16 + qr + 8) * 25 + cg + 1] = cA[nf][3];
    }
    __syncwarp();
    // ---- epilogue: positional-value term + store ----
#pragma unroll
    for (int df = 0; df < 4; df++)
#pragma unroll
        for (int r = 0; r < 4; r++) {
            int ii = qr + (r >> 1) * 8;
            int d  = 8 * df + 2 * qc + (r & 1);
            int ig = i0 + ii;
            float o2 = 0.f;
#pragma unroll
            for (int c = 0; c < 24; c++) {
                int m = (c - ig) % 48; if (m < 0) m += 48;
                o2 += A_s[(n * 16 + ii) * 25 + c] * g_P[m * 256 + n * 32 + d];
            }
            g_att[((size_t)b * TT + ig) * CCH + n * 32 + d] = oacc[df][r] + o2;
        }
}

// ---------- k4 ----------
__global__ __launch_bounds__(256) void k4_fc(const float* __restrict__ x,
                                             const float* __restrict__ w,
                                             const float* __restrict__ bias) {
    int b = blockIdx.z, o0 = blockIdx.y * 64, i0 = blockIdx.x * 64;
    __shared__ float As[16][68], Bs[16][68];
    float acc[4][4] = {};
    int tid = threadIdx.x, tx = tid % 16, ty = tid / 16;
    const float* att = g_att + (size_t)b * TT * CCH;
    for (int c0 = 0; c0 < 256; c0 += 16) {
        int row = tid >> 2, cc = (tid & 3) * 4;
        float4 wv = *(const float4*)&w[(o0 + row) * 256 + c0 + cc];
        As[cc + 0][row] = wv.x; As[cc + 1][row] = wv.y;
        As[cc + 2][row] = wv.z; As[cc + 3][row] = wv.w;
        float4 av = *(const float4*)&att[(i0 + row) * 256 + c0 + cc];
        Bs[cc + 0][row] = av.x; Bs[cc + 1][row] = av.y;
        Bs[cc + 2][row] = av.z; Bs[cc + 3][row] = av.w;
        __syncthreads();
#pragma unroll
        for (int kk = 0; kk < 16; kk++) {
            float a[4], bv[4];
            *(float4*)a  = *(const float4*)&As[kk][ty * 4];
            *(float4*)bv = *(const float4*)&Bs[kk][tx * 4];
#pragma unroll
            for (int r = 0; r < 4; r++)
#pragma unroll
                for (int s = 0; s < 4; s++) acc[r][s] += a[r] * bv[s];
        }
        __syncthreads();
    }
#pragma unroll
    for (int r = 0; r < 4; r++) {
        int o = o0 + ty * 4 + r;
        float bv = bias[o];
        float4 xv = *(const float4*)&x[((size_t)b * CCH + o) * TT + i0 + tx * 4];
        *(float4*)&g_y[((size_t)b * CCH + o) * TT + i0 + tx * 4] =
            make_float4(acc[r][0] + bv + xv.x, acc[r][1] + bv + xv.y,
                        acc[r][2] + bv + xv.z, acc[r][3] + bv + xv.w);
    }
}

__global__ void k5_gnstats() {
    int bid = blockIdx.x, b = bid >> 4, g = bid & 15;
    const float* yp = g_y + ((size_t)(b * CCH + g * 16)) * TT;
    int tid = threadIdx.x;
    float s = 0.f, sq = 0.f;
    for (int idx = tid; idx < 16 * TT; idx += 256) { float v = yp[idx]; s += v; sq += v * v; }
#pragma unroll
    for (int off = 16; off > 0; off >>= 1) {
        s  += __shfl_down_sync(0xffffffffu, s, off);
        sq += __shfl_down_sync(0xffffffffu, sq, off);
    }
    __shared__ float rs[8], rq[8];
    if ((tid & 31) == 0) { rs[tid >> 5] = s; rq[tid >> 5] = sq; }
    __syncthreads();
    if (tid == 0) {
        float S = 0.f, Q = 0.f;
#pragma unroll
        for (int w = 0; w < 8; w++) { S += rs[w]; Q += rq[w]; }
        float mu = S / 9216.f;
        float var = Q / 9216.f - mu * mu;
        g_mu[bid] = mu;
        g_rstd[bid] = rsqrtf(var + GN_EPS);
    }
}

__global__ void k6_gnapply(float* __restrict__ out, const float* __restrict__ gw,
                           const float* __restrict__ gb) {
    int idx = blockIdx.x * 256 + threadIdx.x;
    int o = (idx / TT) & 255;
    int b = idx / (TT * CCH);
    float mu = g_mu[b * 16 + (o >> 4)], rstd = g_rstd[b * 16 + (o >> 4)];
    out[idx] = (g_y[idx] - mu) * rstd * gw[o] + gb[o];
}

extern "C" void kernel_launch(void* const* d_in, const int* in_sizes, int n_in,
                              void* d_out, int out_size) {
    const float* x     = (const float*)d_in[0];
    const float* qkv_w = (const float*)d_in[1];
    const float* qkv_b = (const float*)d_in[2];
    const float* rh_k  = (const float*)d_in[3];
    const float* rw_k  = (const float*)d_in[4];
    const float* rh_v  = (const float*)d_in[5];
    const float* rw_v  = (const float*)d_in[6];
    const float* fc_w  = (const float*)d_in[7];
    const float* fc_b  = (const float*)d_in[8];
    const float* gn_w  = (const float*)d_in[9];
    const float* gn_b  = (const float*)d_in[10];
    float* out = (float*)d_out;

    cudaFuncSetAttribute(k3_attn, cudaFuncAttributeMaxDynamicSharedMemorySize, 42496);

    k0_prep<<<95, 256>>>(rh_v, rw_v, rh_k, rw_k);
    k1_qkv<<<dim3(9, 12, BB), 256>>>(x, qkv_w, qkv_b);
    kE_gemm<<<dim3(9, 128), 256>>>();
    k3_attn<<<dim3(36, BB), 256, 42496>>>();
    k4_fc<<<dim3(9, 4, BB), 256>>>(x, fc_w, fc_b);
    k5_gnstats<<<256, 256>>>();
    k6_gnapply<<<9216, 256>>>(out, gn_w, gn_b);
}